// round 11
// baseline (speedup 1.0000x reference)
#include <cuda_runtime.h>
#include <math.h>
#include <stdint.h>

// Shapes fixed by dataset: T=4096, H=2048, F=1408, E=8, K=2
constexpr int MAX_E = 8;
constexpr int MAX_T = 4096;
constexpr int MAX_F = 1408;
constexpr int MAX_H = 2048;

constexpr int BM = 128, BK = 32;
constexpr int SA = 36;                       // padded smem row stride (words)
constexpr uint32_t A_TILE_U  = 128 * SA;
constexpr uint32_t B64_U     = 64 * SA;
constexpr uint32_t B128_U    = 128 * SA;
constexpr uint32_t A_BYTES   = A_TILE_U * 4;
constexpr uint32_t UP_STAGE_U = A_TILE_U + 2 * B64_U;
constexpr uint32_t DN_STAGE_U = A_TILE_U + B128_U;
constexpr uint32_t UP_STAGE_B = UP_STAGE_U * 4;
constexpr uint32_t DN_STAGE_B = DN_STAGE_U * 4;
constexpr uint32_t UP_SMEM = 3 * UP_STAGE_B + 512;      // 111104 -> 2 CTAs/SM
constexpr uint32_t DN_SMEM = 3 * DN_STAGE_B + 1024;     // 111616 -> 2 CTAs/SM

// ---------------- scratch (static; no allocations allowed) ----------------
__device__ int      g_cnt[MAX_E];
__device__ int      g_tok[MAX_E * MAX_T];
__device__ float    g_gw [MAX_E * MAX_T];
__device__ uint32_t g_act_s[(size_t)MAX_T * MAX_F];
__device__ uint32_t g_act_e[(size_t)MAX_E * MAX_T * MAX_F];
__device__ float    g_routed[(size_t)MAX_T * MAX_H];   // routed-expert accumulator
__device__ uint32_t c_x  [(size_t)MAX_T * MAX_H];
__device__ uint32_t c_ws1[(size_t)MAX_F * MAX_H];
__device__ uint32_t c_ws3[(size_t)MAX_F * MAX_H];
__device__ uint32_t c_ws2[(size_t)MAX_H * MAX_F];
__device__ uint32_t c_we1[(size_t)MAX_E * MAX_F * MAX_H];
__device__ uint32_t c_we3[(size_t)MAX_E * MAX_F * MAX_H];
__device__ uint32_t c_we2[(size_t)MAX_E * MAX_H * MAX_F];

// ---------------- helpers ----------------
__device__ __forceinline__ uint32_t s2u(const void* p) {
    uint32_t a;
    asm("{ .reg .u64 t; cvta.to.shared.u64 t, %1; cvt.u32.u64 %0, t; }" : "=r"(a) : "l"(p));
    return a;
}
__device__ __forceinline__ uint4 tf32x4(float4 v) {
    uint4 u;
    asm("cvt.rna.tf32.f32 %0, %1;" : "=r"(u.x) : "f"(v.x));
    asm("cvt.rna.tf32.f32 %0, %1;" : "=r"(u.y) : "f"(v.y));
    asm("cvt.rna.tf32.f32 %0, %1;" : "=r"(u.z) : "f"(v.z));
    asm("cvt.rna.tf32.f32 %0, %1;" : "=r"(u.w) : "f"(v.w));
    return u;
}
__device__ __forceinline__ uint32_t tf32_1(float v) {
    uint32_t u;
    asm("cvt.rna.tf32.f32 %0, %1;" : "=r"(u) : "f"(v));
    return u;
}
__device__ __forceinline__ void mma8(float c[4], const uint32_t a[4], const uint32_t b[2]) {
    asm volatile(
        "mma.sync.aligned.m16n8k8.row.col.f32.tf32.tf32.f32 "
        "{%0,%1,%2,%3}, {%4,%5,%6,%7}, {%8,%9}, {%0,%1,%2,%3};"
        : "+f"(c[0]), "+f"(c[1]), "+f"(c[2]), "+f"(c[3])
        : "r"(a[0]), "r"(a[1]), "r"(a[2]), "r"(a[3]), "r"(b[0]), "r"(b[1]));
}
#define LDSM4(r, a) asm volatile( \
    "ldmatrix.sync.aligned.m8n8.x4.shared.b16 {%0,%1,%2,%3}, [%4];" \
    : "=r"((r)[0]), "=r"((r)[1]), "=r"((r)[2]), "=r"((r)[3]) : "r"(a))
__device__ __forceinline__ void cpa16(uint32_t dst, const uint32_t* src) {
    asm volatile("cp.async.cg.shared.global [%0], [%1], 16;" :: "r"(dst), "l"(src));
}
#define CP_COMMIT() asm volatile("cp.async.commit_group;" ::: "memory")
#define CP_WAIT1()  asm volatile("cp.async.wait_group 1;" ::: "memory")
__device__ __forceinline__ float silu(float x) { return x / (1.f + __expf(-x)); }

// ---------------- kernel: tf32-round a tensor ----------------
__global__ void conv_kernel(const float* __restrict__ in, uint32_t* __restrict__ out, size_t n) {
    size_t i = ((size_t)blockIdx.x * blockDim.x + threadIdx.x) * 4;
    if (i < n) *(uint4*)(out + i) = tf32x4(*(const float4*)(in + i));
}

// ---------------- kernel: zero counters ----------------
__global__ void zero_cnt_kernel() {
    if (threadIdx.x < MAX_E) g_cnt[threadIdx.x] = 0;
}

// ---------------- kernel: zero routed accumulator ----------------
__global__ void zero_routed_kernel(size_t n) {
    size_t i = ((size_t)blockIdx.x * blockDim.x + threadIdx.x) * 4;
    if (i < n) {
        float4 z; z.x = 0.f; z.y = 0.f; z.z = 0.f; z.w = 0.f;
        *(float4*)(g_routed + i) = z;
    }
}

// ---------------- kernel: OUT = OUT + routed ----------------
__global__ void final_add_kernel(float* __restrict__ out, size_t n) {
    size_t i = ((size_t)blockIdx.x * blockDim.x + threadIdx.x) * 4;
    if (i < n) {
        float4 a = *(const float4*)(out + i);
        float4 b = *(const float4*)(g_routed + i);
        a.x += b.x; a.y += b.y; a.z += b.z; a.w += b.w;
        *(float4*)(out + i) = a;
    }
}

// ---------------- kernel: gating + top-2 routing ----------------
__global__ void gate_kernel(const float* __restrict__ x,
                            const float* __restrict__ gw,
                            const float* __restrict__ bias,
                            int T, int Hd, int E) {
    int t = blockIdx.x;
    int w = threadIdx.x >> 5, lane = threadIdx.x & 31;
    __shared__ float sc[MAX_E];
    if (w < E) {
        const float* xr = x + (size_t)t * Hd;
        const float* gr = gw + (size_t)w * Hd;
        float s = 0.f;
        for (int i = lane; i < Hd; i += 32) s += xr[i] * gr[i];
        #pragma unroll
        for (int o = 16; o; o >>= 1) s += __shfl_down_sync(0xffffffffu, s, o);
        if (lane == 0) sc[w] = s;
    }
    __syncthreads();
    if (threadIdx.x == 0) {
        float score[MAX_E], rt[MAX_E];
        for (int e = 0; e < E; e++) {
            score[e] = 1.f / (1.f + expf(-sc[e]));
            rt[e] = score[e] + bias[e];
        }
        int b1 = 0;
        for (int e = 1; e < E; e++) if (rt[e] > rt[b1]) b1 = e;
        int b2 = -1;
        for (int e = 0; e < E; e++) {
            if (e == b1) continue;
            if (b2 < 0 || rt[e] > rt[b2]) b2 = e;
        }
        float s1 = score[b1], s2 = score[b2];
        float inv = 1.f / (s1 + s2);
        int p1 = atomicAdd(&g_cnt[b1], 1);
        g_tok[b1 * T + p1] = t; g_gw[b1 * T + p1] = s1 * inv;
        int p2 = atomicAdd(&g_cnt[b2], 1);
        g_tok[b2 * T + p2] = t; g_gw[b2 * T + p2] = s2 * inv;
    }
}

// ---------------- up-projection: dual tf32 mma + fused SwiGLU ----------------
template<bool ROUTED>
__global__ void __launch_bounds__(128, 2)
up_mma(const uint32_t* __restrict__ X, const uint32_t* __restrict__ W1a,
       const uint32_t* __restrict__ W3a, int T, int H, int F, int eArg)
{
    extern __shared__ __align__(16) uint32_t sm[];
    const int e     = ROUTED ? eArg : 0;
    const int valid = ROUTED ? g_cnt[e] : T;
    const int row0  = blockIdx.y * BM;
    if (row0 >= valid) return;
    const int col0  = blockIdx.x * 64;
    const int tid   = threadIdx.x, lane = tid & 31, wid = tid >> 5;
    const int wm    = wid >> 1, wn = wid & 1, grp = lane >> 2, tig = lane & 3;
    const uint32_t sb = s2u(sm);

    int* stok = (int*)(sm + 3 * UP_STAGE_U);
    if (ROUTED) {
        int i = row0 + tid; if (i >= valid) i = valid - 1;
        stok[tid] = g_tok[e * T + i];
    }
    __syncthreads();

    const uint32_t* W1 = W1a + (size_t)e * F * H;
    const uint32_t* W3 = W3a + (size_t)e * F * H;
    uint32_t* ACT = ROUTED ? (g_act_e + (size_t)e * T * F) : g_act_s;

    const int r16 = tid >> 3, c4 = tid & 7;
    int atok[8];
    #pragma unroll
    for (int i = 0; i < 8; i++) {
        int r = r16 + 16 * i;
        atok[i] = ROUTED ? stok[r] : (row0 + r);
    }
    const uint32_t* b1base = W1 + (size_t)(col0 + r16) * H + c4 * 4;
    const uint32_t* b3base = W3 + (size_t)(col0 + r16) * H + c4 * 4;
    const uint32_t aoff0 = (uint32_t)(r16 * SA + c4 * 4) * 4;
    const uint32_t rstep = 16u * SA * 4u;

    const int lrow = lane & 7;
    uint32_t aAddr[4];
    #pragma unroll
    for (int mt = 0; mt < 4; mt++) {
        int row = wm * 64 + mt * 16 + lrow + 8 * ((lane >> 3) & 1);
        aAddr[mt] = sb + (uint32_t)(row * SA + 4 * (lane >> 4)) * 4;
    }
    uint32_t b1Addr[2], b3Addr[2];
    #pragma unroll
    for (int p = 0; p < 2; p++) {
        int row = wn * 32 + p * 16 + lrow + 8 * (lane >> 4);
        uint32_t off = (uint32_t)(row * SA + 4 * ((lane >> 3) & 1)) * 4;
        b1Addr[p] = sb + A_BYTES + off;
        b3Addr[p] = sb + A_BYTES + B64_U * 4 + off;
    }

    const int nch = H / BK;
    auto load_stage = [&](int c) {
        uint32_t dbase = sb + (uint32_t)(c % 3) * UP_STAGE_B;
        int k0 = c * BK;
        #pragma unroll
        for (int i = 0; i < 8; i++)
            cpa16(dbase + aoff0 + i * rstep, X + (size_t)atok[i] * H + k0 + c4 * 4);
        #pragma unroll
        for (int i = 0; i < 4; i++) {
            cpa16(dbase + A_BYTES + aoff0 + i * rstep, b1base + (size_t)(16 * i) * H + k0);
            cpa16(dbase + A_BYTES + B64_U * 4 + aoff0 + i * rstep, b3base + (size_t)(16 * i) * H + k0);
        }
    };

    float acc1[4][4][4] = {}, acc3[4][4][4] = {};

    load_stage(0); CP_COMMIT();
    load_stage(1); CP_COMMIT();

    for (int c = 0; c < nch; ++c) {
        CP_WAIT1();
        __syncthreads();
        if (c + 2 < nch) load_stage(c + 2);
        CP_COMMIT();

        const uint32_t stof = (uint32_t)(c % 3) * UP_STAGE_B;
        #pragma unroll
        for (int j = 0; j < 4; j++) {
            uint32_t af[4][4];
            #pragma unroll
            for (int mt = 0; mt < 4; mt++) LDSM4(af[mt], aAddr[mt] + stof + 32u * j);
            uint32_t bf1[2][4], bf3[2][4];
            #pragma unroll
            for (int p = 0; p < 2; p++) {
                LDSM4(bf1[p], b1Addr[p] + stof + 32u * j);
                LDSM4(bf3[p], b3Addr[p] + stof + 32u * j);
            }
            #pragma unroll
            for (int nt = 0; nt < 4; nt++) {
                const int pp = nt >> 1, q = nt & 1;
                uint32_t x1[2] = { bf1[pp][2 * q], bf1[pp][2 * q + 1] };
                uint32_t x3[2] = { bf3[pp][2 * q], bf3[pp][2 * q + 1] };
                #pragma unroll
                for (int mt = 0; mt < 4; mt++) {
                    mma8(acc1[mt][nt], af[mt], x1);
                    mma8(acc3[mt][nt], af[mt], x3);
                }
            }
        }
    }

    #pragma unroll
    for (int mt = 0; mt < 4; mt++) {
        #pragma unroll
        for (int nt = 0; nt < 4; nt++) {
            int cA = col0 + wn * 32 + nt * 8 + 2 * tig;
            #pragma unroll
            for (int half = 0; half < 2; half++) {
                int r = row0 + wm * 64 + mt * 16 + grp + 8 * half;
                if (r >= valid) continue;
                float ox = silu(acc1[mt][nt][2 * half])     * acc3[mt][nt][2 * half];
                float oy = silu(acc1[mt][nt][2 * half + 1]) * acc3[mt][nt][2 * half + 1];
                uint2 u; u.x = tf32_1(ox); u.y = tf32_1(oy);
                *(uint2*)(ACT + (size_t)r * F + cA) = u;
            }
        }
    }
}

// ---------------- down-projection: tf32 mma, plain store or gated scatter ----------------
template<bool ROUTED>
__global__ void __launch_bounds__(128, 2)
down_mma(const uint32_t* __restrict__ W2a, float* __restrict__ OUT, int T, int H, int F, int eArg)
{
    extern __shared__ __align__(16) uint32_t sm[];
    const int e     = ROUTED ? eArg : 0;
    const int valid = ROUTED ? g_cnt[e] : T;
    const int row0  = blockIdx.y * BM;
    if (row0 >= valid) return;
    const int col0  = blockIdx.x * 128;
    const int tid   = threadIdx.x, lane = tid & 31, wid = tid >> 5;
    const int wm    = wid >> 1, wn = wid & 1, grp = lane >> 2, tig = lane & 3;
    const uint32_t sb = s2u(sm);

    int*   stok = (int*)  (sm + 3 * DN_STAGE_U);
    float* sgw  = (float*)(sm + 3 * DN_STAGE_U + 128);
    if (ROUTED) {
        int i = row0 + tid; if (i >= valid) i = valid - 1;
        stok[tid] = g_tok[e * T + i];
        sgw[tid]  = g_gw [e * T + i];
    }
    __syncthreads();

    const uint32_t* ACT = ROUTED ? (g_act_e + (size_t)e * T * F) : g_act_s;
    const uint32_t* W2  = W2a + (size_t)e * H * F;

    const int r16 = tid >> 3, c4 = tid & 7;
    const uint32_t* abase = ACT + (size_t)(row0 + r16) * F + c4 * 4;  // rows >= valid: stale finite scratch, discarded
    const uint32_t* bbase = W2 + (size_t)(col0 + r16) * F + c4 * 4;
    const uint32_t aoff0 = (uint32_t)(r16 * SA + c4 * 4) * 4;
    const uint32_t rstep = 16u * SA * 4u;

    const int lrow = lane & 7;
    uint32_t aAddr[4];
    #pragma unroll
    for (int mt = 0; mt < 4; mt++) {
        int row = wm * 64 + mt * 16 + lrow + 8 * ((lane >> 3) & 1);
        aAddr[mt] = sb + (uint32_t)(row * SA + 4 * (lane >> 4)) * 4;
    }
    uint32_t bAddr[4];
    #pragma unroll
    for (int p = 0; p < 4; p++) {
        int row = wn * 64 + p * 16 + lrow + 8 * (lane >> 4);
        bAddr[p] = sb + A_BYTES + (uint32_t)(row * SA + 4 * ((lane >> 3) & 1)) * 4;
    }

    const int nch = F / BK;
    auto load_stage = [&](int c) {
        uint32_t dbase = sb + (uint32_t)(c % 3) * DN_STAGE_B;
        int k0 = c * BK;
        #pragma unroll
        for (int i = 0; i < 8; i++)
            cpa16(dbase + aoff0 + i * rstep, abase + (size_t)(16 * i) * F + k0);
        #pragma unroll
        for (int i = 0; i < 8; i++)
            cpa16(dbase + A_BYTES + aoff0 + i * rstep, bbase + (size_t)(16 * i) * F + k0);
    };

    float acc[4][8][4] = {};

    load_stage(0); CP_COMMIT();
    load_stage(1); CP_COMMIT();

    for (int c = 0; c < nch; ++c) {
        CP_WAIT1();
        __syncthreads();
        if (c + 2 < nch) load_stage(c + 2);
        CP_COMMIT();

        const uint32_t stof = (uint32_t)(c % 3) * DN_STAGE_B;
        #pragma unroll
        for (int j = 0; j < 4; j++) {
            uint32_t af[4][4];
            #pragma unroll
            for (int mt = 0; mt < 4; mt++) LDSM4(af[mt], aAddr[mt] + stof + 32u * j);
            uint32_t bf[4][4];
            #pragma unroll
            for (int p = 0; p < 4; p++) LDSM4(bf[p], bAddr[p] + stof + 32u * j);
            #pragma unroll
            for (int nt = 0; nt < 8; nt++) {
                const int pp = nt >> 1, q = nt & 1;
                uint32_t xb[2] = { bf[pp][2 * q], bf[pp][2 * q + 1] };
                #pragma unroll
                for (int mt = 0; mt < 4; mt++) mma8(acc[mt][nt], af[mt], xb);
            }
        }
    }

    #pragma unroll
    for (int mt = 0; mt < 4; mt++) {
        #pragma unroll
        for (int nt = 0; nt < 8; nt++) {
            int cA = col0 + wn * 64 + nt * 8 + 2 * tig;
            #pragma unroll
            for (int half = 0; half < 2; half++) {
                int rloc = wm * 64 + mt * 16 + grp + 8 * half;
                int r = row0 + rloc;
                if (r >= valid) continue;
                float v0 = acc[mt][nt][2 * half], v1 = acc[mt][nt][2 * half + 1];
                if (!ROUTED) {
                    float2 o; o.x = v0; o.y = v1;
                    *(float2*)(OUT + (size_t)r * H + cA) = o;
                } else {
                    int tok = stok[rloc]; float g = sgw[rloc];
                    float* dst = OUT + (size_t)tok * H + cA;
                    atomicAdd(dst,     g * v0);
                    atomicAdd(dst + 1, g * v1);
                }
            }
        }
    }
}

// ---------------- launch: per-expert pipelined multi-stream graph ----------------
extern "C" void kernel_launch(void* const* d_in, const int* in_sizes, int n_in,
                              void* d_out, int out_size) {
    const float* x    = (const float*)d_in[0];
    const float* gw   = (const float*)d_in[1];
    const float* bias = (const float*)d_in[2];
    const float* ws1  = (const float*)d_in[3];
    const float* ws2  = (const float*)d_in[4];
    const float* ws3  = (const float*)d_in[5];
    const float* we1  = (const float*)d_in[6];
    const float* we2  = (const float*)d_in[7];
    const float* we3  = (const float*)d_in[8];
    float* out = (float*)d_out;

    const int E  = in_sizes[2];
    const int Hd = in_sizes[1] / E;
    const int F  = in_sizes[3] / Hd;
    const int T  = in_sizes[0] / Hd;

    cudaFuncSetAttribute(up_mma<false>,   cudaFuncAttributeMaxDynamicSharedMemorySize, UP_SMEM);
    cudaFuncSetAttribute(up_mma<true>,    cudaFuncAttributeMaxDynamicSharedMemorySize, UP_SMEM);
    cudaFuncSetAttribute(down_mma<false>, cudaFuncAttributeMaxDynamicSharedMemorySize, DN_SMEM);
    cudaFuncSetAttribute(down_mma<true>,  cudaFuncAttributeMaxDynamicSharedMemorySize, DN_SMEM);

    uint32_t *p_cx, *p_cws1, *p_cws3, *p_cws2, *p_cwe1, *p_cwe3, *p_cwe2;
    float* p_routed;
    cudaGetSymbolAddress((void**)&p_cx,   c_x);
    cudaGetSymbolAddress((void**)&p_cws1, c_ws1);
    cudaGetSymbolAddress((void**)&p_cws3, c_ws3);
    cudaGetSymbolAddress((void**)&p_cws2, c_ws2);
    cudaGetSymbolAddress((void**)&p_cwe1, c_we1);
    cudaGetSymbolAddress((void**)&p_cwe3, c_we3);
    cudaGetSymbolAddress((void**)&p_cwe2, c_we2);
    cudaGetSymbolAddress((void**)&p_routed, g_routed);

    // streams/events created once (host-side resources; no device allocations)
    static cudaStream_t s1 = nullptr, s2 = nullptr, s3 = nullptr;
    static cudaEvent_t e0 = nullptr, ex = nullptr, eg = nullptr, e1 = nullptr, e2 = nullptr;
    static cudaEvent_t evu[MAX_E], evd[MAX_E];
    if (!s1) {
        cudaStreamCreateWithFlags(&s1, cudaStreamNonBlocking);
        cudaStreamCreateWithFlags(&s2, cudaStreamNonBlocking);
        cudaStreamCreateWithFlags(&s3, cudaStreamNonBlocking);
        cudaEventCreateWithFlags(&e0, cudaEventDisableTiming);
        cudaEventCreateWithFlags(&ex, cudaEventDisableTiming);
        cudaEventCreateWithFlags(&eg, cudaEventDisableTiming);
        cudaEventCreateWithFlags(&e1, cudaEventDisableTiming);
        cudaEventCreateWithFlags(&e2, cudaEventDisableTiming);
        for (int e = 0; e < MAX_E; e++) {
            cudaEventCreateWithFlags(&evu[e], cudaEventDisableTiming);
            cudaEventCreateWithFlags(&evd[e], cudaEventDisableTiming);
        }
    }

    auto conv = [](cudaStream_t s, const float* in, uint32_t* o, size_t n) {
        conv_kernel<<<(unsigned)((n / 4 + 255) / 256), 256, 0, s>>>(in, o, n);
    };
    const size_t nOut = (size_t)T * Hd;
    const size_t nW13 = (size_t)F * Hd;          // one expert's W1 or W3
    const size_t nW2  = (size_t)Hd * F;

    // ---- fork from capture (default) stream ----
    zero_cnt_kernel<<<1, 32>>>();
    cudaEventRecord(e0, 0);
    cudaStreamWaitEvent(s1, e0, 0);
    cudaStreamWaitEvent(s2, e0, 0);
    cudaStreamWaitEvent(s3, e0, 0);

    // S0: gating (needs raw x only)
    gate_kernel<<<T, 256>>>(x, gw, bias, T, Hd, E);
    cudaEventRecord(eg, 0);

    // S1: shared-expert chain
    conv(s1, x, p_cx, (size_t)T * Hd);
    cudaEventRecord(ex, s1);                       // converted x (needed by up_e)
    conv(s1, ws1, p_cws1, nW13);
    conv(s1, ws3, p_cws3, nW13);
    conv(s1, ws2, p_cws2, nW2);
    {
        dim3 blk(128);
        up_mma<false><<<dim3(F / 64, T / BM), blk, UP_SMEM, s1>>>(p_cx, p_cws1, p_cws3, T, Hd, F, 0);
        down_mma<false><<<dim3(Hd / 128, T / BM), blk, DN_SMEM, s1>>>(p_cws2, out, T, Hd, F, 0);
    }
    cudaEventRecord(e1, s1);

    // S3: per-expert weight conversion pipeline
    for (int e = 0; e < E; e++) {
        conv(s3, we1 + (size_t)e * nW13, p_cwe1 + (size_t)e * nW13, nW13);
        conv(s3, we3 + (size_t)e * nW13, p_cwe3 + (size_t)e * nW13, nW13);
        cudaEventRecord(evu[e], s3);
    }
    for (int e = 0; e < E; e++) {
        conv(s3, we2 + (size_t)e * nW2, p_cwe2 + (size_t)e * nW2, nW2);
        cudaEventRecord(evd[e], s3);
    }

    // S2: routed GEMMs, per expert, pipelined against S3's conversions
    zero_routed_kernel<<<(unsigned)((nOut / 4 + 255) / 256), 256, 0, s2>>>(nOut);
    cudaStreamWaitEvent(s2, ex, 0);                // converted x
    cudaStreamWaitEvent(s2, eg, 0);                // routing lists
    {
        dim3 blk(128);
        for (int e = 0; e < E; e++) {
            cudaStreamWaitEvent(s2, evu[e], 0);
            up_mma<true><<<dim3(F / 64, T / BM), blk, UP_SMEM, s2>>>(p_cx, p_cwe1, p_cwe3, T, Hd, F, e);
        }
        for (int e = 0; e < E; e++) {
            cudaStreamWaitEvent(s2, evd[e], 0);
            down_mma<true><<<dim3(Hd / 128, T / BM), blk, DN_SMEM, s2>>>(p_cwe2, p_routed, T, Hd, F, e);
        }
    }
    cudaEventRecord(e2, s2);

    // ---- join on capture stream ----
    cudaStreamWaitEvent(0, e1, 0);
    cudaStreamWaitEvent(0, e2, 0);
    final_add_kernel<<<(unsigned)((nOut / 4 + 255) / 256), 256>>>(out, nOut);
}

// round 12
// speedup vs baseline: 1.4824x; 1.4824x over previous
#include <cuda_runtime.h>
#include <math.h>
#include <stdint.h>

// Shapes fixed by dataset: T=4096, H=2048, F=1408, E=8, K=2
constexpr int MAX_E = 8;
constexpr int MAX_T = 4096;
constexpr int MAX_F = 1408;
constexpr int MAX_H = 2048;

constexpr int BM = 128, BK = 32;
constexpr int SA = 36;                       // padded smem row stride (words)
constexpr uint32_t A_TILE_U  = 128 * SA;
constexpr uint32_t B64_U     = 64 * SA;
constexpr uint32_t B128_U    = 128 * SA;
constexpr uint32_t A_BYTES   = A_TILE_U * 4;
constexpr uint32_t UP_STAGE_U = A_TILE_U + 2 * B64_U;
constexpr uint32_t DN_STAGE_U = A_TILE_U + B128_U;
constexpr uint32_t UP_STAGE_B = UP_STAGE_U * 4;
constexpr uint32_t DN_STAGE_B = DN_STAGE_U * 4;
constexpr uint32_t UP_SMEM = 3 * UP_STAGE_B + 512;      // 111104 -> 2 CTAs/SM
constexpr uint32_t DN_SMEM = 3 * DN_STAGE_B + 1024;     // 111616 -> 2 CTAs/SM

// ---------------- scratch (static; no allocations allowed) ----------------
__device__ int      g_cnt[MAX_E];
__device__ int      g_tok[MAX_E * MAX_T];
__device__ float    g_gw [MAX_E * MAX_T];
__device__ uint32_t g_act_s[(size_t)MAX_T * MAX_F];
__device__ uint32_t g_act_e[(size_t)MAX_E * MAX_T * MAX_F];
__device__ float    g_routed[(size_t)MAX_T * MAX_H];   // routed-expert accumulator
__device__ uint32_t c_x  [(size_t)MAX_T * MAX_H];
__device__ uint32_t c_ws1[(size_t)MAX_F * MAX_H];
__device__ uint32_t c_ws3[(size_t)MAX_F * MAX_H];
__device__ uint32_t c_ws2[(size_t)MAX_H * MAX_F];
__device__ uint32_t c_we1[(size_t)MAX_E * MAX_F * MAX_H];
__device__ uint32_t c_we3[(size_t)MAX_E * MAX_F * MAX_H];
__device__ uint32_t c_we2[(size_t)MAX_E * MAX_H * MAX_F];

// ---------------- helpers ----------------
__device__ __forceinline__ uint32_t s2u(const void* p) {
    uint32_t a;
    asm("{ .reg .u64 t; cvta.to.shared.u64 t, %1; cvt.u32.u64 %0, t; }" : "=r"(a) : "l"(p));
    return a;
}
__device__ __forceinline__ uint4 tf32x4(float4 v) {
    uint4 u;
    asm("cvt.rna.tf32.f32 %0, %1;" : "=r"(u.x) : "f"(v.x));
    asm("cvt.rna.tf32.f32 %0, %1;" : "=r"(u.y) : "f"(v.y));
    asm("cvt.rna.tf32.f32 %0, %1;" : "=r"(u.z) : "f"(v.z));
    asm("cvt.rna.tf32.f32 %0, %1;" : "=r"(u.w) : "f"(v.w));
    return u;
}
__device__ __forceinline__ uint32_t tf32_1(float v) {
    uint32_t u;
    asm("cvt.rna.tf32.f32 %0, %1;" : "=r"(u) : "f"(v));
    return u;
}
__device__ __forceinline__ void mma8(float c[4], const uint32_t a[4], const uint32_t b[2]) {
    asm volatile(
        "mma.sync.aligned.m16n8k8.row.col.f32.tf32.tf32.f32 "
        "{%0,%1,%2,%3}, {%4,%5,%6,%7}, {%8,%9}, {%0,%1,%2,%3};"
        : "+f"(c[0]), "+f"(c[1]), "+f"(c[2]), "+f"(c[3])
        : "r"(a[0]), "r"(a[1]), "r"(a[2]), "r"(a[3]), "r"(b[0]), "r"(b[1]));
}
#define LDSM4(r, a) asm volatile( \
    "ldmatrix.sync.aligned.m8n8.x4.shared.b16 {%0,%1,%2,%3}, [%4];" \
    : "=r"((r)[0]), "=r"((r)[1]), "=r"((r)[2]), "=r"((r)[3]) : "r"(a))
__device__ __forceinline__ void cpa16(uint32_t dst, const uint32_t* src) {
    asm volatile("cp.async.cg.shared.global [%0], [%1], 16;" :: "r"(dst), "l"(src));
}
#define CP_COMMIT() asm volatile("cp.async.commit_group;" ::: "memory")
#define CP_WAIT1()  asm volatile("cp.async.wait_group 1;" ::: "memory")
__device__ __forceinline__ float silu(float x) { return x / (1.f + __expf(-x)); }

// ---------------- kernel: tf32-round a tensor ----------------
__global__ void conv_kernel(const float* __restrict__ in, uint32_t* __restrict__ out, size_t n) {
    size_t i = ((size_t)blockIdx.x * blockDim.x + threadIdx.x) * 4;
    if (i < n) *(uint4*)(out + i) = tf32x4(*(const float4*)(in + i));
}

// ---------------- kernel: zero counters ----------------
__global__ void zero_cnt_kernel() {
    if (threadIdx.x < MAX_E) g_cnt[threadIdx.x] = 0;
}

// ---------------- kernel: zero routed accumulator ----------------
__global__ void zero_routed_kernel(size_t n) {
    size_t i = ((size_t)blockIdx.x * blockDim.x + threadIdx.x) * 4;
    if (i < n) {
        float4 z; z.x = 0.f; z.y = 0.f; z.z = 0.f; z.w = 0.f;
        *(float4*)(g_routed + i) = z;
    }
}

// ---------------- kernel: OUT = OUT + routed ----------------
__global__ void final_add_kernel(float* __restrict__ out, size_t n) {
    size_t i = ((size_t)blockIdx.x * blockDim.x + threadIdx.x) * 4;
    if (i < n) {
        float4 a = *(const float4*)(out + i);
        float4 b = *(const float4*)(g_routed + i);
        a.x += b.x; a.y += b.y; a.z += b.z; a.w += b.w;
        *(float4*)(out + i) = a;
    }
}

// ---------------- kernel: gating + top-2 routing ----------------
__global__ void gate_kernel(const float* __restrict__ x,
                            const float* __restrict__ gw,
                            const float* __restrict__ bias,
                            int T, int Hd, int E) {
    int t = blockIdx.x;
    int w = threadIdx.x >> 5, lane = threadIdx.x & 31;
    __shared__ float sc[MAX_E];
    if (w < E) {
        const float* xr = x + (size_t)t * Hd;
        const float* gr = gw + (size_t)w * Hd;
        float s = 0.f;
        for (int i = lane; i < Hd; i += 32) s += xr[i] * gr[i];
        #pragma unroll
        for (int o = 16; o; o >>= 1) s += __shfl_down_sync(0xffffffffu, s, o);
        if (lane == 0) sc[w] = s;
    }
    __syncthreads();
    if (threadIdx.x == 0) {
        float score[MAX_E], rt[MAX_E];
        for (int e = 0; e < E; e++) {
            score[e] = 1.f / (1.f + expf(-sc[e]));
            rt[e] = score[e] + bias[e];
        }
        int b1 = 0;
        for (int e = 1; e < E; e++) if (rt[e] > rt[b1]) b1 = e;
        int b2 = -1;
        for (int e = 0; e < E; e++) {
            if (e == b1) continue;
            if (b2 < 0 || rt[e] > rt[b2]) b2 = e;
        }
        float s1 = score[b1], s2 = score[b2];
        float inv = 1.f / (s1 + s2);
        int p1 = atomicAdd(&g_cnt[b1], 1);
        g_tok[b1 * T + p1] = t; g_gw[b1 * T + p1] = s1 * inv;
        int p2 = atomicAdd(&g_cnt[b2], 1);
        g_tok[b2 * T + p2] = t; g_gw[b2 * T + p2] = s2 * inv;
    }
}

// ---------------- up-projection: dual tf32 mma + fused SwiGLU ----------------
template<bool ROUTED>
__global__ void __launch_bounds__(128, 2)
up_mma(const uint32_t* __restrict__ X, const uint32_t* __restrict__ W1a,
       const uint32_t* __restrict__ W3a, int T, int H, int F)
{
    extern __shared__ __align__(16) uint32_t sm[];
    const int e     = ROUTED ? blockIdx.z : 0;
    const int valid = ROUTED ? g_cnt[e] : T;
    const int row0  = blockIdx.y * BM;
    if (row0 >= valid) return;
    const int col0  = blockIdx.x * 64;
    const int tid   = threadIdx.x, lane = tid & 31, wid = tid >> 5;
    const int wm    = wid >> 1, wn = wid & 1, grp = lane >> 2, tig = lane & 3;
    const uint32_t sb = s2u(sm);

    int* stok = (int*)(sm + 3 * UP_STAGE_U);
    if (ROUTED) {
        int i = row0 + tid; if (i >= valid) i = valid - 1;
        stok[tid] = g_tok[e * T + i];
    }
    __syncthreads();

    const uint32_t* W1 = W1a + (size_t)e * F * H;
    const uint32_t* W3 = W3a + (size_t)e * F * H;
    uint32_t* ACT = ROUTED ? (g_act_e + (size_t)e * T * F) : g_act_s;

    const int r16 = tid >> 3, c4 = tid & 7;
    int atok[8];
    #pragma unroll
    for (int i = 0; i < 8; i++) {
        int r = r16 + 16 * i;
        atok[i] = ROUTED ? stok[r] : (row0 + r);
    }
    const uint32_t* b1base = W1 + (size_t)(col0 + r16) * H + c4 * 4;
    const uint32_t* b3base = W3 + (size_t)(col0 + r16) * H + c4 * 4;
    const uint32_t aoff0 = (uint32_t)(r16 * SA + c4 * 4) * 4;
    const uint32_t rstep = 16u * SA * 4u;

    const int lrow = lane & 7;
    uint32_t aAddr[4];
    #pragma unroll
    for (int mt = 0; mt < 4; mt++) {
        int row = wm * 64 + mt * 16 + lrow + 8 * ((lane >> 3) & 1);
        aAddr[mt] = sb + (uint32_t)(row * SA + 4 * (lane >> 4)) * 4;
    }
    uint32_t b1Addr[2], b3Addr[2];
    #pragma unroll
    for (int p = 0; p < 2; p++) {
        int row = wn * 32 + p * 16 + lrow + 8 * (lane >> 4);
        uint32_t off = (uint32_t)(row * SA + 4 * ((lane >> 3) & 1)) * 4;
        b1Addr[p] = sb + A_BYTES + off;
        b3Addr[p] = sb + A_BYTES + B64_U * 4 + off;
    }

    const int nch = H / BK;
    auto load_stage = [&](int c) {
        uint32_t dbase = sb + (uint32_t)(c % 3) * UP_STAGE_B;
        int k0 = c * BK;
        #pragma unroll
        for (int i = 0; i < 8; i++)
            cpa16(dbase + aoff0 + i * rstep, X + (size_t)atok[i] * H + k0 + c4 * 4);
        #pragma unroll
        for (int i = 0; i < 4; i++) {
            cpa16(dbase + A_BYTES + aoff0 + i * rstep, b1base + (size_t)(16 * i) * H + k0);
            cpa16(dbase + A_BYTES + B64_U * 4 + aoff0 + i * rstep, b3base + (size_t)(16 * i) * H + k0);
        }
    };

    float acc1[4][4][4] = {}, acc3[4][4][4] = {};

    load_stage(0); CP_COMMIT();
    load_stage(1); CP_COMMIT();

    for (int c = 0; c < nch; ++c) {
        CP_WAIT1();
        __syncthreads();
        if (c + 2 < nch) load_stage(c + 2);
        CP_COMMIT();

        const uint32_t stof = (uint32_t)(c % 3) * UP_STAGE_B;
        #pragma unroll
        for (int j = 0; j < 4; j++) {
            uint32_t af[4][4];
            #pragma unroll
            for (int mt = 0; mt < 4; mt++) LDSM4(af[mt], aAddr[mt] + stof + 32u * j);
            uint32_t bf1[2][4], bf3[2][4];
            #pragma unroll
            for (int p = 0; p < 2; p++) {
                LDSM4(bf1[p], b1Addr[p] + stof + 32u * j);
                LDSM4(bf3[p], b3Addr[p] + stof + 32u * j);
            }
            #pragma unroll
            for (int nt = 0; nt < 4; nt++) {
                const int pp = nt >> 1, q = nt & 1;
                uint32_t x1[2] = { bf1[pp][2 * q], bf1[pp][2 * q + 1] };
                uint32_t x3[2] = { bf3[pp][2 * q], bf3[pp][2 * q + 1] };
                #pragma unroll
                for (int mt = 0; mt < 4; mt++) {
                    mma8(acc1[mt][nt], af[mt], x1);
                    mma8(acc3[mt][nt], af[mt], x3);
                }
            }
        }
    }

    #pragma unroll
    for (int mt = 0; mt < 4; mt++) {
        #pragma unroll
        for (int nt = 0; nt < 4; nt++) {
            int cA = col0 + wn * 32 + nt * 8 + 2 * tig;
            #pragma unroll
            for (int half = 0; half < 2; half++) {
                int r = row0 + wm * 64 + mt * 16 + grp + 8 * half;
                if (r >= valid) continue;
                float ox = silu(acc1[mt][nt][2 * half])     * acc3[mt][nt][2 * half];
                float oy = silu(acc1[mt][nt][2 * half + 1]) * acc3[mt][nt][2 * half + 1];
                uint2 u; u.x = tf32_1(ox); u.y = tf32_1(oy);
                *(uint2*)(ACT + (size_t)r * F + cA) = u;
            }
        }
    }
}

// ---------------- down-projection: tf32 mma, plain store or gated scatter ----------------
template<bool ROUTED>
__global__ void __launch_bounds__(128, 2)
down_mma(const uint32_t* __restrict__ W2a, float* __restrict__ OUT, int T, int H, int F)
{
    extern __shared__ __align__(16) uint32_t sm[];
    const int e     = ROUTED ? blockIdx.z : 0;
    const int valid = ROUTED ? g_cnt[e] : T;
    const int row0  = blockIdx.y * BM;
    if (row0 >= valid) return;
    const int col0  = blockIdx.x * 128;
    const int tid   = threadIdx.x, lane = tid & 31, wid = tid >> 5;
    const int wm    = wid >> 1, wn = wid & 1, grp = lane >> 2, tig = lane & 3;
    const uint32_t sb = s2u(sm);

    int*   stok = (int*)  (sm + 3 * DN_STAGE_U);
    float* sgw  = (float*)(sm + 3 * DN_STAGE_U + 128);
    if (ROUTED) {
        int i = row0 + tid; if (i >= valid) i = valid - 1;
        stok[tid] = g_tok[e * T + i];
        sgw[tid]  = g_gw [e * T + i];
    }
    __syncthreads();

    const uint32_t* ACT = ROUTED ? (g_act_e + (size_t)e * T * F) : g_act_s;
    const uint32_t* W2  = W2a + (size_t)e * H * F;

    const int r16 = tid >> 3, c4 = tid & 7;
    const uint32_t* abase = ACT + (size_t)(row0 + r16) * F + c4 * 4;  // rows >= valid: stale finite scratch, discarded
    const uint32_t* bbase = W2 + (size_t)(col0 + r16) * F + c4 * 4;
    const uint32_t aoff0 = (uint32_t)(r16 * SA + c4 * 4) * 4;
    const uint32_t rstep = 16u * SA * 4u;

    const int lrow = lane & 7;
    uint32_t aAddr[4];
    #pragma unroll
    for (int mt = 0; mt < 4; mt++) {
        int row = wm * 64 + mt * 16 + lrow + 8 * ((lane >> 3) & 1);
        aAddr[mt] = sb + (uint32_t)(row * SA + 4 * (lane >> 4)) * 4;
    }
    uint32_t bAddr[4];
    #pragma unroll
    for (int p = 0; p < 4; p++) {
        int row = wn * 64 + p * 16 + lrow + 8 * (lane >> 4);
        bAddr[p] = sb + A_BYTES + (uint32_t)(row * SA + 4 * ((lane >> 3) & 1)) * 4;
    }

    const int nch = F / BK;
    auto load_stage = [&](int c) {
        uint32_t dbase = sb + (uint32_t)(c % 3) * DN_STAGE_B;
        int k0 = c * BK;
        #pragma unroll
        for (int i = 0; i < 8; i++)
            cpa16(dbase + aoff0 + i * rstep, abase + (size_t)(16 * i) * F + k0);
        #pragma unroll
        for (int i = 0; i < 8; i++)
            cpa16(dbase + A_BYTES + aoff0 + i * rstep, bbase + (size_t)(16 * i) * F + k0);
    };

    float acc[4][8][4] = {};

    load_stage(0); CP_COMMIT();
    load_stage(1); CP_COMMIT();

    for (int c = 0; c < nch; ++c) {
        CP_WAIT1();
        __syncthreads();
        if (c + 2 < nch) load_stage(c + 2);
        CP_COMMIT();

        const uint32_t stof = (uint32_t)(c % 3) * DN_STAGE_B;
        #pragma unroll
        for (int j = 0; j < 4; j++) {
            uint32_t af[4][4];
            #pragma unroll
            for (int mt = 0; mt < 4; mt++) LDSM4(af[mt], aAddr[mt] + stof + 32u * j);
            uint32_t bf[4][4];
            #pragma unroll
            for (int p = 0; p < 4; p++) LDSM4(bf[p], bAddr[p] + stof + 32u * j);
            #pragma unroll
            for (int nt = 0; nt < 8; nt++) {
                const int pp = nt >> 1, q = nt & 1;
                uint32_t xb[2] = { bf[pp][2 * q], bf[pp][2 * q + 1] };
                #pragma unroll
                for (int mt = 0; mt < 4; mt++) mma8(acc[mt][nt], af[mt], xb);
            }
        }
    }

    #pragma unroll
    for (int mt = 0; mt < 4; mt++) {
        #pragma unroll
        for (int nt = 0; nt < 8; nt++) {
            int cA = col0 + wn * 64 + nt * 8 + 2 * tig;
            #pragma unroll
            for (int half = 0; half < 2; half++) {
                int rloc = wm * 64 + mt * 16 + grp + 8 * half;
                int r = row0 + rloc;
                if (r >= valid) continue;
                float v0 = acc[mt][nt][2 * half], v1 = acc[mt][nt][2 * half + 1];
                if (!ROUTED) {
                    float2 o; o.x = v0; o.y = v1;
                    *(float2*)(OUT + (size_t)r * H + cA) = o;
                } else {
                    int tok = stok[rloc]; float g = sgw[rloc];
                    float* dst = OUT + (size_t)tok * H + cA;
                    atomicAdd(dst,     g * v0);
                    atomicAdd(dst + 1, g * v1);
                }
            }
        }
    }
}

// ---------------- launch: forked multi-stream graph (z-batched GEMMs) ----------------
extern "C" void kernel_launch(void* const* d_in, const int* in_sizes, int n_in,
                              void* d_out, int out_size) {
    const float* x    = (const float*)d_in[0];
    const float* gw   = (const float*)d_in[1];
    const float* bias = (const float*)d_in[2];
    const float* ws1  = (const float*)d_in[3];
    const float* ws2  = (const float*)d_in[4];
    const float* ws3  = (const float*)d_in[5];
    const float* we1  = (const float*)d_in[6];
    const float* we2  = (const float*)d_in[7];
    const float* we3  = (const float*)d_in[8];
    float* out = (float*)d_out;

    const int E  = in_sizes[2];
    const int Hd = in_sizes[1] / E;
    const int F  = in_sizes[3] / Hd;
    const int T  = in_sizes[0] / Hd;

    cudaFuncSetAttribute(up_mma<false>,   cudaFuncAttributeMaxDynamicSharedMemorySize, UP_SMEM);
    cudaFuncSetAttribute(up_mma<true>,    cudaFuncAttributeMaxDynamicSharedMemorySize, UP_SMEM);
    cudaFuncSetAttribute(down_mma<false>, cudaFuncAttributeMaxDynamicSharedMemorySize, DN_SMEM);
    cudaFuncSetAttribute(down_mma<true>,  cudaFuncAttributeMaxDynamicSharedMemorySize, DN_SMEM);

    uint32_t *p_cx, *p_cws1, *p_cws3, *p_cws2, *p_cwe1, *p_cwe3, *p_cwe2;
    float* p_routed;
    cudaGetSymbolAddress((void**)&p_cx,   c_x);
    cudaGetSymbolAddress((void**)&p_cws1, c_ws1);
    cudaGetSymbolAddress((void**)&p_cws3, c_ws3);
    cudaGetSymbolAddress((void**)&p_cws2, c_ws2);
    cudaGetSymbolAddress((void**)&p_cwe1, c_we1);
    cudaGetSymbolAddress((void**)&p_cwe3, c_we3);
    cudaGetSymbolAddress((void**)&p_cwe2, c_we2);
    cudaGetSymbolAddress((void**)&p_routed, g_routed);

    // streams/events created once (host-side resources; no device allocations)
    static cudaStream_t s1 = nullptr, s2 = nullptr, s3 = nullptr;
    static cudaEvent_t e0 = nullptr, ex = nullptr, eg = nullptr;
    static cudaEvent_t e1 = nullptr, e2 = nullptr, evA = nullptr, evB = nullptr;
    if (!s1) {
        cudaStreamCreateWithFlags(&s1, cudaStreamNonBlocking);
        cudaStreamCreateWithFlags(&s2, cudaStreamNonBlocking);
        cudaStreamCreateWithFlags(&s3, cudaStreamNonBlocking);
        cudaEventCreateWithFlags(&e0,  cudaEventDisableTiming);
        cudaEventCreateWithFlags(&ex,  cudaEventDisableTiming);
        cudaEventCreateWithFlags(&eg,  cudaEventDisableTiming);
        cudaEventCreateWithFlags(&e1,  cudaEventDisableTiming);
        cudaEventCreateWithFlags(&e2,  cudaEventDisableTiming);
        cudaEventCreateWithFlags(&evA, cudaEventDisableTiming);
        cudaEventCreateWithFlags(&evB, cudaEventDisableTiming);
    }

    auto conv = [](cudaStream_t s, const float* in, uint32_t* o, size_t n) {
        conv_kernel<<<(unsigned)((n / 4 + 255) / 256), 256, 0, s>>>(in, o, n);
    };
    const size_t nOut = (size_t)T * Hd;

    // ---- fork from capture (default) stream ----
    zero_cnt_kernel<<<1, 32>>>();
    cudaEventRecord(e0, 0);
    cudaStreamWaitEvent(s1, e0, 0);
    cudaStreamWaitEvent(s2, e0, 0);
    cudaStreamWaitEvent(s3, e0, 0);

    // S0: gating (needs raw x only)
    gate_kernel<<<T, 256>>>(x, gw, bias, T, Hd, E);
    cudaEventRecord(eg, 0);

    // S3: expert-weight conversions (concurrent with s1's GEMMs)
    conv(s3, we1, p_cwe1, (size_t)E * F * Hd);
    conv(s3, we3, p_cwe3, (size_t)E * F * Hd);
    cudaEventRecord(evA, s3);                      // up_e gate
    conv(s3, we2, p_cwe2, (size_t)E * Hd * F);
    cudaEventRecord(evB, s3);                      // down_e gate

    // S1: shared-expert chain
    conv(s1, x, p_cx, (size_t)T * Hd);
    cudaEventRecord(ex, s1);                       // converted x (needed by up_e)
    conv(s1, ws1, p_cws1, (size_t)F * Hd);
    conv(s1, ws3, p_cws3, (size_t)F * Hd);
    conv(s1, ws2, p_cws2, (size_t)Hd * F);
    {
        dim3 blk(128);
        up_mma<false><<<dim3(F / 64, T / BM), blk, UP_SMEM, s1>>>(p_cx, p_cws1, p_cws3, T, Hd, F);
        down_mma<false><<<dim3(Hd / 128, T / BM), blk, DN_SMEM, s1>>>(p_cws2, out, T, Hd, F);
    }
    cudaEventRecord(e1, s1);

    // S2: routed chain (z-batched full-machine launches)
    zero_routed_kernel<<<(unsigned)((nOut / 4 + 255) / 256), 256, 0, s2>>>(nOut);
    cudaStreamWaitEvent(s2, ex, 0);                // converted x
    cudaStreamWaitEvent(s2, eg, 0);                // routing lists
    cudaStreamWaitEvent(s2, evA, 0);               // converted we1/we3
    {
        dim3 blk(128);
        up_mma<true><<<dim3(F / 64, T / BM, E), blk, UP_SMEM, s2>>>(p_cx, p_cwe1, p_cwe3, T, Hd, F);
        cudaStreamWaitEvent(s2, evB, 0);           // converted we2
        down_mma<true><<<dim3(Hd / 128, T / BM, E), blk, DN_SMEM, s2>>>(p_cwe2, p_routed, T, Hd, F);
    }
    cudaEventRecord(e2, s2);

    // ---- join on capture stream ----
    cudaStreamWaitEvent(0, e1, 0);
    cudaStreamWaitEvent(0, e2, 0);
    final_add_kernel<<<(unsigned)((nOut / 4 + 255) / 256), 256>>>(out, nOut);
}

// round 13
// speedup vs baseline: 1.6548x; 1.1163x over previous
#include <cuda_runtime.h>
#include <math.h>
#include <stdint.h>

// Shapes fixed by dataset: T=4096, H=2048, F=1408, E=8, K=2
constexpr int MAX_E = 8;
constexpr int MAX_T = 4096;
constexpr int MAX_F = 1408;
constexpr int MAX_H = 2048;

constexpr int BM = 128, BK = 32;
constexpr int SA = 36;                       // padded smem row stride (words)
constexpr uint32_t A_TILE_U  = 128 * SA;
constexpr uint32_t B64_U     = 64 * SA;
constexpr uint32_t B128_U    = 128 * SA;
constexpr uint32_t A_BYTES   = A_TILE_U * 4;
constexpr uint32_t UP_STAGE_U = A_TILE_U + 2 * B64_U;   // 9216 words = 36864 B
constexpr uint32_t DN_STAGE_U = A_TILE_U + B128_U;      // 9216 words
constexpr uint32_t UP_STAGE_B = UP_STAGE_U * 4;
constexpr uint32_t DN_STAGE_B = DN_STAGE_U * 4;
constexpr uint32_t UP_SMEM = 2 * UP_STAGE_B + 512;      // 74240  -> 3 CTAs/SM
constexpr uint32_t DN_SMEM = 2 * DN_STAGE_B + 1024;     // 74752  -> 3 CTAs/SM

// ---------------- scratch (static; no allocations allowed) ----------------
__device__ int      g_cnt[MAX_E];
__device__ int      g_tok[MAX_E * MAX_T];
__device__ float    g_gw [MAX_E * MAX_T];
__device__ uint32_t g_act_s[(size_t)MAX_T * MAX_F];
__device__ uint32_t g_act_e[(size_t)MAX_E * MAX_T * MAX_F];
__device__ float    g_routed[(size_t)MAX_T * MAX_H];   // routed-expert accumulator
__device__ uint32_t c_x  [(size_t)MAX_T * MAX_H];
__device__ uint32_t c_ws1[(size_t)MAX_F * MAX_H];
__device__ uint32_t c_ws3[(size_t)MAX_F * MAX_H];
__device__ uint32_t c_ws2[(size_t)MAX_H * MAX_F];
__device__ uint32_t c_we1[(size_t)MAX_E * MAX_F * MAX_H];
__device__ uint32_t c_we3[(size_t)MAX_E * MAX_F * MAX_H];
__device__ uint32_t c_we2[(size_t)MAX_E * MAX_H * MAX_F];

// ---------------- helpers ----------------
__device__ __forceinline__ uint32_t s2u(const void* p) {
    uint32_t a;
    asm("{ .reg .u64 t; cvta.to.shared.u64 t, %1; cvt.u32.u64 %0, t; }" : "=r"(a) : "l"(p));
    return a;
}
__device__ __forceinline__ uint4 tf32x4(float4 v) {
    uint4 u;
    asm("cvt.rna.tf32.f32 %0, %1;" : "=r"(u.x) : "f"(v.x));
    asm("cvt.rna.tf32.f32 %0, %1;" : "=r"(u.y) : "f"(v.y));
    asm("cvt.rna.tf32.f32 %0, %1;" : "=r"(u.z) : "f"(v.z));
    asm("cvt.rna.tf32.f32 %0, %1;" : "=r"(u.w) : "f"(v.w));
    return u;
}
__device__ __forceinline__ uint32_t tf32_1(float v) {
    uint32_t u;
    asm("cvt.rna.tf32.f32 %0, %1;" : "=r"(u) : "f"(v));
    return u;
}
__device__ __forceinline__ void mma8(float c[4], const uint32_t a[4], const uint32_t b[2]) {
    asm volatile(
        "mma.sync.aligned.m16n8k8.row.col.f32.tf32.tf32.f32 "
        "{%0,%1,%2,%3}, {%4,%5,%6,%7}, {%8,%9}, {%0,%1,%2,%3};"
        : "+f"(c[0]), "+f"(c[1]), "+f"(c[2]), "+f"(c[3])
        : "r"(a[0]), "r"(a[1]), "r"(a[2]), "r"(a[3]), "r"(b[0]), "r"(b[1]));
}
#define LDSM4(r, a) asm volatile( \
    "ldmatrix.sync.aligned.m8n8.x4.shared.b16 {%0,%1,%2,%3}, [%4];" \
    : "=r"((r)[0]), "=r"((r)[1]), "=r"((r)[2]), "=r"((r)[3]) : "r"(a))
__device__ __forceinline__ void cpa16(uint32_t dst, const uint32_t* src) {
    asm volatile("cp.async.cg.shared.global [%0], [%1], 16;" :: "r"(dst), "l"(src));
}
#define CP_COMMIT() asm volatile("cp.async.commit_group;" ::: "memory")
#define CP_WAIT0()  asm volatile("cp.async.wait_group 0;" ::: "memory")
__device__ __forceinline__ float silu(float x) { return x / (1.f + __expf(-x)); }

// ---------------- kernel: tf32-round a tensor ----------------
__global__ void conv_kernel(const float* __restrict__ in, uint32_t* __restrict__ out, size_t n) {
    size_t i = ((size_t)blockIdx.x * blockDim.x + threadIdx.x) * 4;
    if (i < n) *(uint4*)(out + i) = tf32x4(*(const float4*)(in + i));
}

// ---------------- kernel: zero counters ----------------
__global__ void zero_cnt_kernel() {
    if (threadIdx.x < MAX_E) g_cnt[threadIdx.x] = 0;
}

// ---------------- kernel: zero routed accumulator ----------------
__global__ void zero_routed_kernel(size_t n) {
    size_t i = ((size_t)blockIdx.x * blockDim.x + threadIdx.x) * 4;
    if (i < n) {
        float4 z; z.x = 0.f; z.y = 0.f; z.z = 0.f; z.w = 0.f;
        *(float4*)(g_routed + i) = z;
    }
}

// ---------------- kernel: OUT = OUT + routed ----------------
__global__ void final_add_kernel(float* __restrict__ out, size_t n) {
    size_t i = ((size_t)blockIdx.x * blockDim.x + threadIdx.x) * 4;
    if (i < n) {
        float4 a = *(const float4*)(out + i);
        float4 b = *(const float4*)(g_routed + i);
        a.x += b.x; a.y += b.y; a.z += b.z; a.w += b.w;
        *(float4*)(out + i) = a;
    }
}

// ---------------- kernel: gating + top-2 routing ----------------
__global__ void gate_kernel(const float* __restrict__ x,
                            const float* __restrict__ gw,
                            const float* __restrict__ bias,
                            int T, int Hd, int E) {
    int t = blockIdx.x;
    int w = threadIdx.x >> 5, lane = threadIdx.x & 31;
    __shared__ float sc[MAX_E];
    if (w < E) {
        const float* xr = x + (size_t)t * Hd;
        const float* gr = gw + (size_t)w * Hd;
        float s = 0.f;
        for (int i = lane; i < Hd; i += 32) s += xr[i] * gr[i];
        #pragma unroll
        for (int o = 16; o; o >>= 1) s += __shfl_down_sync(0xffffffffu, s, o);
        if (lane == 0) sc[w] = s;
    }
    __syncthreads();
    if (threadIdx.x == 0) {
        float score[MAX_E], rt[MAX_E];
        for (int e = 0; e < E; e++) {
            score[e] = 1.f / (1.f + expf(-sc[e]));
            rt[e] = score[e] + bias[e];
        }
        int b1 = 0;
        for (int e = 1; e < E; e++) if (rt[e] > rt[b1]) b1 = e;
        int b2 = -1;
        for (int e = 0; e < E; e++) {
            if (e == b1) continue;
            if (b2 < 0 || rt[e] > rt[b2]) b2 = e;
        }
        float s1 = score[b1], s2 = score[b2];
        float inv = 1.f / (s1 + s2);
        int p1 = atomicAdd(&g_cnt[b1], 1);
        g_tok[b1 * T + p1] = t; g_gw[b1 * T + p1] = s1 * inv;
        int p2 = atomicAdd(&g_cnt[b2], 1);
        g_tok[b2 * T + p2] = t; g_gw[b2 * T + p2] = s2 * inv;
    }
}

// ---------------- up-projection: dual tf32 mma + fused SwiGLU ----------------
// 128 threads, 4 warps (2x2); warp tile 64x(32+32); 2-stage pipeline; 3 CTAs/SM.
template<bool ROUTED>
__global__ void __launch_bounds__(128, 3)
up_mma(const uint32_t* __restrict__ X, const uint32_t* __restrict__ W1a,
       const uint32_t* __restrict__ W3a, int T, int H, int F)
{
    extern __shared__ __align__(16) uint32_t sm[];
    const int e     = ROUTED ? blockIdx.z : 0;
    const int valid = ROUTED ? g_cnt[e] : T;
    const int row0  = blockIdx.y * BM;
    if (row0 >= valid) return;
    const int col0  = blockIdx.x * 64;
    const int tid   = threadIdx.x, lane = tid & 31, wid = tid >> 5;
    const int wm    = wid >> 1, wn = wid & 1, grp = lane >> 2, tig = lane & 3;
    const uint32_t sb = s2u(sm);

    int* stok = (int*)(sm + 2 * UP_STAGE_U);
    if (ROUTED) {
        int i = row0 + tid; if (i >= valid) i = valid - 1;
        stok[tid] = g_tok[e * T + i];
    }
    __syncthreads();

    const uint32_t* W1 = W1a + (size_t)e * F * H;
    const uint32_t* W3 = W3a + (size_t)e * F * H;
    uint32_t* ACT = ROUTED ? (g_act_e + (size_t)e * T * F) : g_act_s;

    const int r16 = tid >> 3, c4 = tid & 7;
    const uint32_t* b1base = W1 + (size_t)(col0 + r16) * H + c4 * 4;
    const uint32_t* b3base = W3 + (size_t)(col0 + r16) * H + c4 * 4;
    const uint32_t aoff0 = (uint32_t)(r16 * SA + c4 * 4) * 4;
    const uint32_t rstep = 16u * SA * 4u;

    const int lrow = lane & 7;
    uint32_t aAddr[4];
    #pragma unroll
    for (int mt = 0; mt < 4; mt++) {
        int row = wm * 64 + mt * 16 + lrow + 8 * ((lane >> 3) & 1);
        aAddr[mt] = sb + (uint32_t)(row * SA + 4 * (lane >> 4)) * 4;
    }
    uint32_t b1Addr[2], b3Addr[2];
    #pragma unroll
    for (int p = 0; p < 2; p++) {
        int row = wn * 32 + p * 16 + lrow + 8 * (lane >> 4);
        uint32_t off = (uint32_t)(row * SA + 4 * ((lane >> 3) & 1)) * 4;
        b1Addr[p] = sb + A_BYTES + off;
        b3Addr[p] = sb + A_BYTES + B64_U * 4 + off;
    }

    const int nch = H / BK;
    auto load_stage = [&](int c) {
        uint32_t dbase = sb + (uint32_t)(c & 1) * UP_STAGE_B;
        int k0 = c * BK;
        #pragma unroll
        for (int i = 0; i < 8; i++) {
            int r = r16 + 16 * i;
            int tok = ROUTED ? stok[r] : (row0 + r);
            cpa16(dbase + aoff0 + i * rstep, X + (size_t)tok * H + k0 + c4 * 4);
        }
        #pragma unroll
        for (int i = 0; i < 4; i++) {
            cpa16(dbase + A_BYTES + aoff0 + i * rstep, b1base + (size_t)(16 * i) * H + k0);
            cpa16(dbase + A_BYTES + B64_U * 4 + aoff0 + i * rstep, b3base + (size_t)(16 * i) * H + k0);
        }
    };

    float acc1[4][4][4] = {}, acc3[4][4][4] = {};

    load_stage(0); CP_COMMIT();

    for (int c = 0; c < nch; ++c) {
        CP_WAIT0();
        __syncthreads();
        if (c + 1 < nch) { load_stage(c + 1); CP_COMMIT(); }

        const uint32_t stof = (uint32_t)(c & 1) * UP_STAGE_B;
        #pragma unroll
        for (int j = 0; j < 4; j++) {
            uint32_t af[4][4];
            #pragma unroll
            for (int mt = 0; mt < 4; mt++) LDSM4(af[mt], aAddr[mt] + stof + 32u * j);
            uint32_t bf1[2][4], bf3[2][4];
            #pragma unroll
            for (int p = 0; p < 2; p++) {
                LDSM4(bf1[p], b1Addr[p] + stof + 32u * j);
                LDSM4(bf3[p], b3Addr[p] + stof + 32u * j);
            }
            #pragma unroll
            for (int nt = 0; nt < 4; nt++) {
                const int pp = nt >> 1, q = nt & 1;
                uint32_t x1[2] = { bf1[pp][2 * q], bf1[pp][2 * q + 1] };
                uint32_t x3[2] = { bf3[pp][2 * q], bf3[pp][2 * q + 1] };
                #pragma unroll
                for (int mt = 0; mt < 4; mt++) {
                    mma8(acc1[mt][nt], af[mt], x1);
                    mma8(acc3[mt][nt], af[mt], x3);
                }
            }
        }
    }

    // epilogue: SwiGLU, store tf32-rounded pairs
    #pragma unroll
    for (int mt = 0; mt < 4; mt++) {
        #pragma unroll
        for (int nt = 0; nt < 4; nt++) {
            int cA = col0 + wn * 32 + nt * 8 + 2 * tig;
            #pragma unroll
            for (int half = 0; half < 2; half++) {
                int r = row0 + wm * 64 + mt * 16 + grp + 8 * half;
                if (r >= valid) continue;
                float ox = silu(acc1[mt][nt][2 * half])     * acc3[mt][nt][2 * half];
                float oy = silu(acc1[mt][nt][2 * half + 1]) * acc3[mt][nt][2 * half + 1];
                uint2 u; u.x = tf32_1(ox); u.y = tf32_1(oy);
                *(uint2*)(ACT + (size_t)r * F + cA) = u;
            }
        }
    }
}

// ---------------- down-projection: tf32 mma, plain store or gated scatter ----------------
// 128 threads, 4 warps (2x2); warp tile 64x64; 2-stage pipeline; 3 CTAs/SM.
template<bool ROUTED>
__global__ void __launch_bounds__(128, 3)
down_mma(const uint32_t* __restrict__ W2a, float* __restrict__ OUT, int T, int H, int F)
{
    extern __shared__ __align__(16) uint32_t sm[];
    const int e     = ROUTED ? blockIdx.z : 0;
    const int valid = ROUTED ? g_cnt[e] : T;
    const int row0  = blockIdx.y * BM;
    if (row0 >= valid) return;
    const int col0  = blockIdx.x * 128;
    const int tid   = threadIdx.x, lane = tid & 31, wid = tid >> 5;
    const int wm    = wid >> 1, wn = wid & 1, grp = lane >> 2, tig = lane & 3;
    const uint32_t sb = s2u(sm);

    int*   stok = (int*)  (sm + 2 * DN_STAGE_U);
    float* sgw  = (float*)(sm + 2 * DN_STAGE_U + 128);
    if (ROUTED) {
        int i = row0 + tid; if (i >= valid) i = valid - 1;
        stok[tid] = g_tok[e * T + i];
        sgw[tid]  = g_gw [e * T + i];
    }
    __syncthreads();

    const uint32_t* ACT = ROUTED ? (g_act_e + (size_t)e * T * F) : g_act_s;
    const uint32_t* W2  = W2a + (size_t)e * H * F;

    const int r16 = tid >> 3, c4 = tid & 7;
    const uint32_t* abase = ACT + (size_t)(row0 + r16) * F + c4 * 4;  // rows >= valid: stale finite scratch, discarded
    const uint32_t* bbase = W2 + (size_t)(col0 + r16) * F + c4 * 4;
    const uint32_t aoff0 = (uint32_t)(r16 * SA + c4 * 4) * 4;
    const uint32_t rstep = 16u * SA * 4u;

    const int lrow = lane & 7;
    uint32_t aAddr[4];
    #pragma unroll
    for (int mt = 0; mt < 4; mt++) {
        int row = wm * 64 + mt * 16 + lrow + 8 * ((lane >> 3) & 1);
        aAddr[mt] = sb + (uint32_t)(row * SA + 4 * (lane >> 4)) * 4;
    }
    uint32_t bAddr[4];
    #pragma unroll
    for (int p = 0; p < 4; p++) {
        int row = wn * 64 + p * 16 + lrow + 8 * (lane >> 4);
        bAddr[p] = sb + A_BYTES + (uint32_t)(row * SA + 4 * ((lane >> 3) & 1)) * 4;
    }

    const int nch = F / BK;
    auto load_stage = [&](int c) {
        uint32_t dbase = sb + (uint32_t)(c & 1) * DN_STAGE_B;
        int k0 = c * BK;
        #pragma unroll
        for (int i = 0; i < 8; i++)
            cpa16(dbase + aoff0 + i * rstep, abase + (size_t)(16 * i) * F + k0);
        #pragma unroll
        for (int i = 0; i < 8; i++)
            cpa16(dbase + A_BYTES + aoff0 + i * rstep, bbase + (size_t)(16 * i) * F + k0);
    };

    float acc[4][8][4] = {};

    load_stage(0); CP_COMMIT();

    for (int c = 0; c < nch; ++c) {
        CP_WAIT0();
        __syncthreads();
        if (c + 1 < nch) { load_stage(c + 1); CP_COMMIT(); }

        const uint32_t stof = (uint32_t)(c & 1) * DN_STAGE_B;
        #pragma unroll
        for (int j = 0; j < 4; j++) {
            uint32_t af[4][4];
            #pragma unroll
            for (int mt = 0; mt < 4; mt++) LDSM4(af[mt], aAddr[mt] + stof + 32u * j);
            uint32_t bf[4][4];
            #pragma unroll
            for (int p = 0; p < 4; p++) LDSM4(bf[p], bAddr[p] + stof + 32u * j);
            #pragma unroll
            for (int nt = 0; nt < 8; nt++) {
                const int pp = nt >> 1, q = nt & 1;
                uint32_t xb[2] = { bf[pp][2 * q], bf[pp][2 * q + 1] };
                #pragma unroll
                for (int mt = 0; mt < 4; mt++) mma8(acc[mt][nt], af[mt], xb);
            }
        }
    }

    #pragma unroll
    for (int mt = 0; mt < 4; mt++) {
        #pragma unroll
        for (int nt = 0; nt < 8; nt++) {
            int cA = col0 + wn * 64 + nt * 8 + 2 * tig;
            #pragma unroll
            for (int half = 0; half < 2; half++) {
                int rloc = wm * 64 + mt * 16 + grp + 8 * half;
                int r = row0 + rloc;
                if (r >= valid) continue;
                float v0 = acc[mt][nt][2 * half], v1 = acc[mt][nt][2 * half + 1];
                if (!ROUTED) {
                    float2 o; o.x = v0; o.y = v1;
                    *(float2*)(OUT + (size_t)r * H + cA) = o;
                } else {
                    int tok = stok[rloc]; float g = sgw[rloc];
                    float* dst = OUT + (size_t)tok * H + cA;
                    atomicAdd(dst,     g * v0);
                    atomicAdd(dst + 1, g * v1);
                }
            }
        }
    }
}

// ---------------- launch: forked multi-stream graph (z-batched GEMMs) ----------------
extern "C" void kernel_launch(void* const* d_in, const int* in_sizes, int n_in,
                              void* d_out, int out_size) {
    const float* x    = (const float*)d_in[0];
    const float* gw   = (const float*)d_in[1];
    const float* bias = (const float*)d_in[2];
    const float* ws1  = (const float*)d_in[3];
    const float* ws2  = (const float*)d_in[4];
    const float* ws3  = (const float*)d_in[5];
    const float* we1  = (const float*)d_in[6];
    const float* we2  = (const float*)d_in[7];
    const float* we3  = (const float*)d_in[8];
    float* out = (float*)d_out;

    const int E  = in_sizes[2];
    const int Hd = in_sizes[1] / E;
    const int F  = in_sizes[3] / Hd;
    const int T  = in_sizes[0] / Hd;

    cudaFuncSetAttribute(up_mma<false>,   cudaFuncAttributeMaxDynamicSharedMemorySize, UP_SMEM);
    cudaFuncSetAttribute(up_mma<true>,    cudaFuncAttributeMaxDynamicSharedMemorySize, UP_SMEM);
    cudaFuncSetAttribute(down_mma<false>, cudaFuncAttributeMaxDynamicSharedMemorySize, DN_SMEM);
    cudaFuncSetAttribute(down_mma<true>,  cudaFuncAttributeMaxDynamicSharedMemorySize, DN_SMEM);

    uint32_t *p_cx, *p_cws1, *p_cws3, *p_cws2, *p_cwe1, *p_cwe3, *p_cwe2;
    float* p_routed;
    cudaGetSymbolAddress((void**)&p_cx,   c_x);
    cudaGetSymbolAddress((void**)&p_cws1, c_ws1);
    cudaGetSymbolAddress((void**)&p_cws3, c_ws3);
    cudaGetSymbolAddress((void**)&p_cws2, c_ws2);
    cudaGetSymbolAddress((void**)&p_cwe1, c_we1);
    cudaGetSymbolAddress((void**)&p_cwe3, c_we3);
    cudaGetSymbolAddress((void**)&p_cwe2, c_we2);
    cudaGetSymbolAddress((void**)&p_routed, g_routed);

    // streams/events created once (host-side resources; no device allocations)
    static cudaStream_t s1 = nullptr, s2 = nullptr, s3 = nullptr;
    static cudaEvent_t e0 = nullptr, ex = nullptr, eg = nullptr;
    static cudaEvent_t e1 = nullptr, e2 = nullptr, evA = nullptr, evB = nullptr;
    if (!s1) {
        cudaStreamCreateWithFlags(&s1, cudaStreamNonBlocking);
        cudaStreamCreateWithFlags(&s2, cudaStreamNonBlocking);
        cudaStreamCreateWithFlags(&s3, cudaStreamNonBlocking);
        cudaEventCreateWithFlags(&e0,  cudaEventDisableTiming);
        cudaEventCreateWithFlags(&ex,  cudaEventDisableTiming);
        cudaEventCreateWithFlags(&eg,  cudaEventDisableTiming);
        cudaEventCreateWithFlags(&e1,  cudaEventDisableTiming);
        cudaEventCreateWithFlags(&e2,  cudaEventDisableTiming);
        cudaEventCreateWithFlags(&evA, cudaEventDisableTiming);
        cudaEventCreateWithFlags(&evB, cudaEventDisableTiming);
    }

    auto conv = [](cudaStream_t s, const float* in, uint32_t* o, size_t n) {
        conv_kernel<<<(unsigned)((n / 4 + 255) / 256), 256, 0, s>>>(in, o, n);
    };
    const size_t nOut = (size_t)T * Hd;

    // ---- fork from capture (default) stream ----
    zero_cnt_kernel<<<1, 32>>>();
    cudaEventRecord(e0, 0);
    cudaStreamWaitEvent(s1, e0, 0);
    cudaStreamWaitEvent(s2, e0, 0);
    cudaStreamWaitEvent(s3, e0, 0);

    // S0: gating (needs raw x only)
    gate_kernel<<<T, 256>>>(x, gw, bias, T, Hd, E);
    cudaEventRecord(eg, 0);

    // S3: expert-weight conversions (concurrent with s1's GEMMs)
    conv(s3, we1, p_cwe1, (size_t)E * F * Hd);
    conv(s3, we3, p_cwe3, (size_t)E * F * Hd);
    cudaEventRecord(evA, s3);                      // up_e gate
    conv(s3, we2, p_cwe2, (size_t)E * Hd * F);
    cudaEventRecord(evB, s3);                      // down_e gate

    // S1: shared-expert chain
    conv(s1, x, p_cx, (size_t)T * Hd);
    cudaEventRecord(ex, s1);                       // converted x (needed by up_e)
    conv(s1, ws1, p_cws1, (size_t)F * Hd);
    conv(s1, ws3, p_cws3, (size_t)F * Hd);
    conv(s1, ws2, p_cws2, (size_t)Hd * F);
    {
        dim3 blk(128);
        up_mma<false><<<dim3(F / 64, T / BM), blk, UP_SMEM, s1>>>(p_cx, p_cws1, p_cws3, T, Hd, F);
        down_mma<false><<<dim3(Hd / 128, T / BM), blk, DN_SMEM, s1>>>(p_cws2, out, T, Hd, F);
    }
    cudaEventRecord(e1, s1);

    // S2: routed chain (z-batched full-machine launches)
    zero_routed_kernel<<<(unsigned)((nOut / 4 + 255) / 256), 256, 0, s2>>>(nOut);
    cudaStreamWaitEvent(s2, ex, 0);                // converted x
    cudaStreamWaitEvent(s2, eg, 0);                // routing lists
    cudaStreamWaitEvent(s2, evA, 0);               // converted we1/we3
    {
        dim3 blk(128);
        up_mma<true><<<dim3(F / 64, T / BM, E), blk, UP_SMEM, s2>>>(p_cx, p_cwe1, p_cwe3, T, Hd, F);
        cudaStreamWaitEvent(s2, evB, 0);           // converted we2
        down_mma<true><<<dim3(Hd / 128, T / BM, E), blk, DN_SMEM, s2>>>(p_cwe2, p_routed, T, Hd, F);
    }
    cudaEventRecord(e2, s2);

    // ---- join on capture stream ----
    cudaStreamWaitEvent(0, e1, 0);
    cudaStreamWaitEvent(0, e2, 0);
    final_add_kernel<<<(unsigned)((nOut / 4 + 255) / 256), 256>>>(out, nOut);
}

// round 14
// speedup vs baseline: 1.7052x; 1.0304x over previous
#include <cuda_runtime.h>
#include <math.h>
#include <stdint.h>

// Shapes fixed by dataset: T=4096, H=2048, F=1408, E=8, K=2
constexpr int MAX_E = 8;
constexpr int MAX_T = 4096;
constexpr int MAX_F = 1408;
constexpr int MAX_H = 2048;

constexpr int BM = 128, BK = 32;
constexpr int SA = 36;                       // padded smem row stride (words)
constexpr uint32_t A_TILE_U  = 128 * SA;
constexpr uint32_t B64_U     = 64 * SA;
constexpr uint32_t B128_U    = 128 * SA;
constexpr uint32_t A_BYTES   = A_TILE_U * 4;
constexpr uint32_t UP_STAGE_U = A_TILE_U + 2 * B64_U;   // 9216 words = 36864 B
constexpr uint32_t DN_STAGE_U = A_TILE_U + B128_U;      // 9216 words
constexpr uint32_t UP_STAGE_B = UP_STAGE_U * 4;
constexpr uint32_t DN_STAGE_B = DN_STAGE_U * 4;
constexpr uint32_t UP_SMEM = 2 * UP_STAGE_B + 512;      // 74240  -> 3 CTAs/SM
constexpr uint32_t DN_SMEM = 2 * DN_STAGE_B + 1024;     // 74752  -> 3 CTAs/SM

// ---------------- scratch (static; no allocations allowed) ----------------
__device__ int      g_cnt[MAX_E];
__device__ int      g_tok[MAX_E * MAX_T];
__device__ float    g_gw [MAX_E * MAX_T];
__device__ uint32_t g_act_s[(size_t)MAX_T * MAX_F];
__device__ uint32_t g_act_e[(size_t)MAX_E * MAX_T * MAX_F];
__device__ uint32_t c_x  [(size_t)MAX_T * MAX_H];
__device__ uint32_t c_ws1[(size_t)MAX_F * MAX_H];
__device__ uint32_t c_ws3[(size_t)MAX_F * MAX_H];
__device__ uint32_t c_ws2[(size_t)MAX_H * MAX_F];
__device__ uint32_t c_we1[(size_t)MAX_E * MAX_F * MAX_H];
__device__ uint32_t c_we3[(size_t)MAX_E * MAX_F * MAX_H];
__device__ uint32_t c_we2[(size_t)MAX_E * MAX_H * MAX_F];

// ---------------- helpers ----------------
__device__ __forceinline__ uint32_t s2u(const void* p) {
    uint32_t a;
    asm("{ .reg .u64 t; cvta.to.shared.u64 t, %1; cvt.u32.u64 %0, t; }" : "=r"(a) : "l"(p));
    return a;
}
__device__ __forceinline__ uint4 tf32x4(float4 v) {
    uint4 u;
    asm("cvt.rna.tf32.f32 %0, %1;" : "=r"(u.x) : "f"(v.x));
    asm("cvt.rna.tf32.f32 %0, %1;" : "=r"(u.y) : "f"(v.y));
    asm("cvt.rna.tf32.f32 %0, %1;" : "=r"(u.z) : "f"(v.z));
    asm("cvt.rna.tf32.f32 %0, %1;" : "=r"(u.w) : "f"(v.w));
    return u;
}
__device__ __forceinline__ uint32_t tf32_1(float v) {
    uint32_t u;
    asm("cvt.rna.tf32.f32 %0, %1;" : "=r"(u) : "f"(v));
    return u;
}
__device__ __forceinline__ void mma8(float c[4], const uint32_t a[4], const uint32_t b[2]) {
    asm volatile(
        "mma.sync.aligned.m16n8k8.row.col.f32.tf32.tf32.f32 "
        "{%0,%1,%2,%3}, {%4,%5,%6,%7}, {%8,%9}, {%0,%1,%2,%3};"
        : "+f"(c[0]), "+f"(c[1]), "+f"(c[2]), "+f"(c[3])
        : "r"(a[0]), "r"(a[1]), "r"(a[2]), "r"(a[3]), "r"(b[0]), "r"(b[1]));
}
#define LDSM4(r, a) asm volatile( \
    "ldmatrix.sync.aligned.m8n8.x4.shared.b16 {%0,%1,%2,%3}, [%4];" \
    : "=r"((r)[0]), "=r"((r)[1]), "=r"((r)[2]), "=r"((r)[3]) : "r"(a))
__device__ __forceinline__ void cpa16(uint32_t dst, const uint32_t* src) {
    asm volatile("cp.async.cg.shared.global [%0], [%1], 16;" :: "r"(dst), "l"(src));
}
#define CP_COMMIT() asm volatile("cp.async.commit_group;" ::: "memory")
#define CP_WAIT0()  asm volatile("cp.async.wait_group 0;" ::: "memory")
__device__ __forceinline__ float silu(float x) { return x / (1.f + __expf(-x)); }

// ---------------- kernel: tf32-round a tensor ----------------
__global__ void conv_kernel(const float* __restrict__ in, uint32_t* __restrict__ out, size_t n) {
    size_t i = ((size_t)blockIdx.x * blockDim.x + threadIdx.x) * 4;
    if (i < n) *(uint4*)(out + i) = tf32x4(*(const float4*)(in + i));
}

// ---------------- kernel: zero counters ----------------
__global__ void zero_cnt_kernel() {
    if (threadIdx.x < MAX_E) g_cnt[threadIdx.x] = 0;
}

// ---------------- kernel: zero output ----------------
__global__ void zero_out_kernel(float* __restrict__ out, size_t n) {
    size_t i = ((size_t)blockIdx.x * blockDim.x + threadIdx.x) * 4;
    if (i < n) {
        float4 z; z.x = 0.f; z.y = 0.f; z.z = 0.f; z.w = 0.f;
        *(float4*)(out + i) = z;
    }
}

// ---------------- kernel: gating + top-2 routing (smem-staged x row) ----------------
__global__ void gate_kernel(const float* __restrict__ x,
                            const float* __restrict__ gw,
                            const float* __restrict__ bias,
                            int T, int Hd, int E) {
    int t = blockIdx.x;
    int w = threadIdx.x >> 5, lane = threadIdx.x & 31;
    extern __shared__ float sx[];          // Hd floats + E partials
    float* sc = sx + Hd;
    // stage the token row once
    for (int i = threadIdx.x * 4; i < Hd; i += blockDim.x * 4)
        *(float4*)(sx + i) = *(const float4*)(x + (size_t)t * Hd + i);
    __syncthreads();
    if (w < E) {
        const float* gr = gw + (size_t)w * Hd;
        float s = 0.f;
        for (int i = lane; i < Hd; i += 32) s += sx[i] * gr[i];
        #pragma unroll
        for (int o = 16; o; o >>= 1) s += __shfl_down_sync(0xffffffffu, s, o);
        if (lane == 0) sc[w] = s;
    }
    __syncthreads();
    if (threadIdx.x == 0) {
        float score[MAX_E], rt[MAX_E];
        for (int e = 0; e < E; e++) {
            score[e] = 1.f / (1.f + expf(-sc[e]));
            rt[e] = score[e] + bias[e];
        }
        int b1 = 0;
        for (int e = 1; e < E; e++) if (rt[e] > rt[b1]) b1 = e;
        int b2 = -1;
        for (int e = 0; e < E; e++) {
            if (e == b1) continue;
            if (b2 < 0 || rt[e] > rt[b2]) b2 = e;
        }
        float s1 = score[b1], s2 = score[b2];
        float inv = 1.f / (s1 + s2);
        int p1 = atomicAdd(&g_cnt[b1], 1);
        g_tok[b1 * T + p1] = t; g_gw[b1 * T + p1] = s1 * inv;
        int p2 = atomicAdd(&g_cnt[b2], 1);
        g_tok[b2 * T + p2] = t; g_gw[b2 * T + p2] = s2 * inv;
    }
}

// ---------------- up-projection: dual tf32 mma + fused SwiGLU ----------------
// 128 threads, 4 warps (2x2); warp tile 64x(32+32); 2-stage pipeline; 3 CTAs/SM.
template<bool ROUTED>
__global__ void __launch_bounds__(128, 3)
up_mma(const uint32_t* __restrict__ X, const uint32_t* __restrict__ W1a,
       const uint32_t* __restrict__ W3a, int T, int H, int F)
{
    extern __shared__ __align__(16) uint32_t sm[];
    const int e     = ROUTED ? blockIdx.z : 0;
    const int valid = ROUTED ? g_cnt[e] : T;
    const int row0  = blockIdx.y * BM;
    if (row0 >= valid) return;
    const int col0  = blockIdx.x * 64;
    const int tid   = threadIdx.x, lane = tid & 31, wid = tid >> 5;
    const int wm    = wid >> 1, wn = wid & 1, grp = lane >> 2, tig = lane & 3;
    const uint32_t sb = s2u(sm);

    int* stok = (int*)(sm + 2 * UP_STAGE_U);
    if (ROUTED) {
        int i = row0 + tid; if (i >= valid) i = valid - 1;
        stok[tid] = g_tok[e * T + i];
    }
    __syncthreads();

    const uint32_t* W1 = W1a + (size_t)e * F * H;
    const uint32_t* W3 = W3a + (size_t)e * F * H;
    uint32_t* ACT = ROUTED ? (g_act_e + (size_t)e * T * F) : g_act_s;

    const int r16 = tid >> 3, c4 = tid & 7;
    const uint32_t* b1base = W1 + (size_t)(col0 + r16) * H + c4 * 4;
    const uint32_t* b3base = W3 + (size_t)(col0 + r16) * H + c4 * 4;
    const uint32_t aoff0 = (uint32_t)(r16 * SA + c4 * 4) * 4;
    const uint32_t rstep = 16u * SA * 4u;

    const int lrow = lane & 7;
    uint32_t aAddr[4];
    #pragma unroll
    for (int mt = 0; mt < 4; mt++) {
        int row = wm * 64 + mt * 16 + lrow + 8 * ((lane >> 3) & 1);
        aAddr[mt] = sb + (uint32_t)(row * SA + 4 * (lane >> 4)) * 4;
    }
    uint32_t b1Addr[2], b3Addr[2];
    #pragma unroll
    for (int p = 0; p < 2; p++) {
        int row = wn * 32 + p * 16 + lrow + 8 * (lane >> 4);
        uint32_t off = (uint32_t)(row * SA + 4 * ((lane >> 3) & 1)) * 4;
        b1Addr[p] = sb + A_BYTES + off;
        b3Addr[p] = sb + A_BYTES + B64_U * 4 + off;
    }

    const int nch = H / BK;
    auto load_stage = [&](int c) {
        uint32_t dbase = sb + (uint32_t)(c & 1) * UP_STAGE_B;
        int k0 = c * BK;
        #pragma unroll
        for (int i = 0; i < 8; i++) {
            int r = r16 + 16 * i;
            int tok = ROUTED ? stok[r] : (row0 + r);
            cpa16(dbase + aoff0 + i * rstep, X + (size_t)tok * H + k0 + c4 * 4);
        }
        #pragma unroll
        for (int i = 0; i < 4; i++) {
            cpa16(dbase + A_BYTES + aoff0 + i * rstep, b1base + (size_t)(16 * i) * H + k0);
            cpa16(dbase + A_BYTES + B64_U * 4 + aoff0 + i * rstep, b3base + (size_t)(16 * i) * H + k0);
        }
    };

    float acc1[4][4][4] = {}, acc3[4][4][4] = {};

    load_stage(0); CP_COMMIT();

    for (int c = 0; c < nch; ++c) {
        CP_WAIT0();
        __syncthreads();
        if (c + 1 < nch) { load_stage(c + 1); CP_COMMIT(); }

        const uint32_t stof = (uint32_t)(c & 1) * UP_STAGE_B;
        #pragma unroll
        for (int j = 0; j < 4; j++) {
            uint32_t af[4][4];
            #pragma unroll
            for (int mt = 0; mt < 4; mt++) LDSM4(af[mt], aAddr[mt] + stof + 32u * j);
            uint32_t bf1[2][4], bf3[2][4];
            #pragma unroll
            for (int p = 0; p < 2; p++) {
                LDSM4(bf1[p], b1Addr[p] + stof + 32u * j);
                LDSM4(bf3[p], b3Addr[p] + stof + 32u * j);
            }
            #pragma unroll
            for (int nt = 0; nt < 4; nt++) {
                const int pp = nt >> 1, q = nt & 1;
                uint32_t x1[2] = { bf1[pp][2 * q], bf1[pp][2 * q + 1] };
                uint32_t x3[2] = { bf3[pp][2 * q], bf3[pp][2 * q + 1] };
                #pragma unroll
                for (int mt = 0; mt < 4; mt++) {
                    mma8(acc1[mt][nt], af[mt], x1);
                    mma8(acc3[mt][nt], af[mt], x3);
                }
            }
        }
    }

    // epilogue: SwiGLU, store tf32-rounded pairs
    #pragma unroll
    for (int mt = 0; mt < 4; mt++) {
        #pragma unroll
        for (int nt = 0; nt < 4; nt++) {
            int cA = col0 + wn * 32 + nt * 8 + 2 * tig;
            #pragma unroll
            for (int half = 0; half < 2; half++) {
                int r = row0 + wm * 64 + mt * 16 + grp + 8 * half;
                if (r >= valid) continue;
                float ox = silu(acc1[mt][nt][2 * half])     * acc3[mt][nt][2 * half];
                float oy = silu(acc1[mt][nt][2 * half + 1]) * acc3[mt][nt][2 * half + 1];
                uint2 u; u.x = tf32_1(ox); u.y = tf32_1(oy);
                *(uint2*)(ACT + (size_t)r * F + cA) = u;
            }
        }
    }
}

// ---------------- down-projection: tf32 mma, atomic accumulate into OUT ----------------
// 128 threads, 4 warps (2x2); warp tile 64x64; 2-stage pipeline; 3 CTAs/SM.
template<bool ROUTED>
__global__ void __launch_bounds__(128, 3)
down_mma(const uint32_t* __restrict__ W2a, float* __restrict__ OUT, int T, int H, int F)
{
    extern __shared__ __align__(16) uint32_t sm[];
    const int e     = ROUTED ? blockIdx.z : 0;
    const int valid = ROUTED ? g_cnt[e] : T;
    const int row0  = blockIdx.y * BM;
    if (row0 >= valid) return;
    const int col0  = blockIdx.x * 128;
    const int tid   = threadIdx.x, lane = tid & 31, wid = tid >> 5;
    const int wm    = wid >> 1, wn = wid & 1, grp = lane >> 2, tig = lane & 3;
    const uint32_t sb = s2u(sm);

    int*   stok = (int*)  (sm + 2 * DN_STAGE_U);
    float* sgw  = (float*)(sm + 2 * DN_STAGE_U + 128);
    if (ROUTED) {
        int i = row0 + tid; if (i >= valid) i = valid - 1;
        stok[tid] = g_tok[e * T + i];
        sgw[tid]  = g_gw [e * T + i];
    }
    __syncthreads();

    const uint32_t* ACT = ROUTED ? (g_act_e + (size_t)e * T * F) : g_act_s;
    const uint32_t* W2  = W2a + (size_t)e * H * F;

    const int r16 = tid >> 3, c4 = tid & 7;
    const uint32_t* abase = ACT + (size_t)(row0 + r16) * F + c4 * 4;  // rows >= valid: stale finite scratch, discarded
    const uint32_t* bbase = W2 + (size_t)(col0 + r16) * F + c4 * 4;
    const uint32_t aoff0 = (uint32_t)(r16 * SA + c4 * 4) * 4;
    const uint32_t rstep = 16u * SA * 4u;

    const int lrow = lane & 7;
    uint32_t aAddr[4];
    #pragma unroll
    for (int mt = 0; mt < 4; mt++) {
        int row = wm * 64 + mt * 16 + lrow + 8 * ((lane >> 3) & 1);
        aAddr[mt] = sb + (uint32_t)(row * SA + 4 * (lane >> 4)) * 4;
    }
    uint32_t bAddr[4];
    #pragma unroll
    for (int p = 0; p < 4; p++) {
        int row = wn * 64 + p * 16 + lrow + 8 * (lane >> 4);
        bAddr[p] = sb + A_BYTES + (uint32_t)(row * SA + 4 * ((lane >> 3) & 1)) * 4;
    }

    const int nch = F / BK;
    auto load_stage = [&](int c) {
        uint32_t dbase = sb + (uint32_t)(c & 1) * DN_STAGE_B;
        int k0 = c * BK;
        #pragma unroll
        for (int i = 0; i < 8; i++)
            cpa16(dbase + aoff0 + i * rstep, abase + (size_t)(16 * i) * F + k0);
        #pragma unroll
        for (int i = 0; i < 8; i++)
            cpa16(dbase + A_BYTES + aoff0 + i * rstep, bbase + (size_t)(16 * i) * F + k0);
    };

    float acc[4][8][4] = {};

    load_stage(0); CP_COMMIT();

    for (int c = 0; c < nch; ++c) {
        CP_WAIT0();
        __syncthreads();
        if (c + 1 < nch) { load_stage(c + 1); CP_COMMIT(); }

        const uint32_t stof = (uint32_t)(c & 1) * DN_STAGE_B;
        #pragma unroll
        for (int j = 0; j < 4; j++) {
            uint32_t af[4][4];
            #pragma unroll
            for (int mt = 0; mt < 4; mt++) LDSM4(af[mt], aAddr[mt] + stof + 32u * j);
            uint32_t bf[4][4];
            #pragma unroll
            for (int p = 0; p < 4; p++) LDSM4(bf[p], bAddr[p] + stof + 32u * j);
            #pragma unroll
            for (int nt = 0; nt < 8; nt++) {
                const int pp = nt >> 1, q = nt & 1;
                uint32_t xb[2] = { bf[pp][2 * q], bf[pp][2 * q + 1] };
                #pragma unroll
                for (int mt = 0; mt < 4; mt++) mma8(acc[mt][nt], af[mt], xb);
            }
        }
    }

    #pragma unroll
    for (int mt = 0; mt < 4; mt++) {
        #pragma unroll
        for (int nt = 0; nt < 8; nt++) {
            int cA = col0 + wn * 64 + nt * 8 + 2 * tig;
            #pragma unroll
            for (int half = 0; half < 2; half++) {
                int rloc = wm * 64 + mt * 16 + grp + 8 * half;
                int r = row0 + rloc;
                if (r >= valid) continue;
                float v0 = acc[mt][nt][2 * half], v1 = acc[mt][nt][2 * half + 1];
                int tok; float g;
                if (ROUTED) { tok = stok[rloc]; g = sgw[rloc]; }
                else        { tok = r;          g = 1.0f;      }
                float* dst = OUT + (size_t)tok * H + cA;
                atomicAdd(dst,     g * v0);
                atomicAdd(dst + 1, g * v1);
            }
        }
    }
}

// ---------------- launch: forked multi-stream graph (z-batched GEMMs) ----------------
extern "C" void kernel_launch(void* const* d_in, const int* in_sizes, int n_in,
                              void* d_out, int out_size) {
    const float* x    = (const float*)d_in[0];
    const float* gw   = (const float*)d_in[1];
    const float* bias = (const float*)d_in[2];
    const float* ws1  = (const float*)d_in[3];
    const float* ws2  = (const float*)d_in[4];
    const float* ws3  = (const float*)d_in[5];
    const float* we1  = (const float*)d_in[6];
    const float* we2  = (const float*)d_in[7];
    const float* we3  = (const float*)d_in[8];
    float* out = (float*)d_out;

    const int E  = in_sizes[2];
    const int Hd = in_sizes[1] / E;
    const int F  = in_sizes[3] / Hd;
    const int T  = in_sizes[0] / Hd;

    cudaFuncSetAttribute(up_mma<false>,   cudaFuncAttributeMaxDynamicSharedMemorySize, UP_SMEM);
    cudaFuncSetAttribute(up_mma<true>,    cudaFuncAttributeMaxDynamicSharedMemorySize, UP_SMEM);
    cudaFuncSetAttribute(down_mma<false>, cudaFuncAttributeMaxDynamicSharedMemorySize, DN_SMEM);
    cudaFuncSetAttribute(down_mma<true>,  cudaFuncAttributeMaxDynamicSharedMemorySize, DN_SMEM);

    uint32_t *p_cx, *p_cws1, *p_cws3, *p_cws2, *p_cwe1, *p_cwe3, *p_cwe2;
    cudaGetSymbolAddress((void**)&p_cx,   c_x);
    cudaGetSymbolAddress((void**)&p_cws1, c_ws1);
    cudaGetSymbolAddress((void**)&p_cws3, c_ws3);
    cudaGetSymbolAddress((void**)&p_cws2, c_ws2);
    cudaGetSymbolAddress((void**)&p_cwe1, c_we1);
    cudaGetSymbolAddress((void**)&p_cwe3, c_we3);
    cudaGetSymbolAddress((void**)&p_cwe2, c_we2);

    // streams/events created once (host-side resources; no device allocations)
    static cudaStream_t s1 = nullptr, s2 = nullptr, s3 = nullptr;
    static cudaEvent_t e0 = nullptr, ex = nullptr, eg = nullptr, ez = nullptr;
    static cudaEvent_t e1 = nullptr, e2 = nullptr, evA = nullptr, evB = nullptr;
    if (!s1) {
        cudaStreamCreateWithFlags(&s1, cudaStreamNonBlocking);
        cudaStreamCreateWithFlags(&s2, cudaStreamNonBlocking);
        cudaStreamCreateWithFlags(&s3, cudaStreamNonBlocking);
        cudaEventCreateWithFlags(&e0,  cudaEventDisableTiming);
        cudaEventCreateWithFlags(&ex,  cudaEventDisableTiming);
        cudaEventCreateWithFlags(&eg,  cudaEventDisableTiming);
        cudaEventCreateWithFlags(&ez,  cudaEventDisableTiming);
        cudaEventCreateWithFlags(&e1,  cudaEventDisableTiming);
        cudaEventCreateWithFlags(&e2,  cudaEventDisableTiming);
        cudaEventCreateWithFlags(&evA, cudaEventDisableTiming);
        cudaEventCreateWithFlags(&evB, cudaEventDisableTiming);
    }

    auto conv = [](cudaStream_t s, const float* in, uint32_t* o, size_t n) {
        conv_kernel<<<(unsigned)((n / 4 + 255) / 256), 256, 0, s>>>(in, o, n);
    };
    const size_t nOut = (size_t)T * Hd;

    // ---- fork from capture (default) stream ----
    zero_cnt_kernel<<<1, 32>>>();
    zero_out_kernel<<<(unsigned)((nOut / 4 + 255) / 256), 256>>>(out, nOut);
    cudaEventRecord(ez, 0);                        // out zeroed (gates both downs)
    cudaStreamWaitEvent(s1, ez, 0);
    cudaStreamWaitEvent(s2, ez, 0);
    cudaStreamWaitEvent(s3, ez, 0);

    // S0: gating (needs raw x only)
    gate_kernel<<<T, 256, (Hd + MAX_E) * 4>>>(x, gw, bias, T, Hd, E);
    cudaEventRecord(eg, 0);

    // S3: expert-weight conversions (concurrent with s1's GEMMs)
    conv(s3, we1, p_cwe1, (size_t)E * F * Hd);
    conv(s3, we3, p_cwe3, (size_t)E * F * Hd);
    cudaEventRecord(evA, s3);                      // up_e gate
    conv(s3, we2, p_cwe2, (size_t)E * Hd * F);
    cudaEventRecord(evB, s3);                      // down_e gate

    // S1: shared-expert chain
    conv(s1, x, p_cx, (size_t)T * Hd);
    cudaEventRecord(ex, s1);                       // converted x (needed by up_e)
    conv(s1, ws1, p_cws1, (size_t)F * Hd);
    conv(s1, ws3, p_cws3, (size_t)F * Hd);
    conv(s1, ws2, p_cws2, (size_t)Hd * F);
    {
        dim3 blk(128);
        up_mma<false><<<dim3(F / 64, T / BM), blk, UP_SMEM, s1>>>(p_cx, p_cws1, p_cws3, T, Hd, F);
        down_mma<false><<<dim3(Hd / 128, T / BM), blk, DN_SMEM, s1>>>(p_cws2, out, T, Hd, F);
    }
    cudaEventRecord(e1, s1);

    // S2: routed chain (z-batched full-machine launches)
    cudaStreamWaitEvent(s2, ex, 0);                // converted x
    cudaStreamWaitEvent(s2, eg, 0);                // routing lists
    cudaStreamWaitEvent(s2, evA, 0);               // converted we1/we3
    {
        dim3 blk(128);
        up_mma<true><<<dim3(F / 64, T / BM, E), blk, UP_SMEM, s2>>>(p_cx, p_cwe1, p_cwe3, T, Hd, F);
        cudaStreamWaitEvent(s2, evB, 0);           // converted we2
        down_mma<true><<<dim3(Hd / 128, T / BM, E), blk, DN_SMEM, s2>>>(p_cwe2, out, T, Hd, F);
    }
    cudaEventRecord(e2, s2);

    // ---- join on capture stream ----
    cudaStreamWaitEvent(0, e1, 0);
    cudaStreamWaitEvent(0, e2, 0);
}

// round 15
// speedup vs baseline: 1.8011x; 1.0563x over previous
#include <cuda_runtime.h>
#include <math.h>
#include <stdint.h>

// Shapes fixed by dataset: T=4096, H=2048, F=1408, E=8, K=2
constexpr int MAX_E = 8;
constexpr int MAX_T = 4096;
constexpr int MAX_F = 1408;
constexpr int MAX_H = 2048;

constexpr int BM = 128, BK = 32;
constexpr int SA = 36;                       // padded smem row stride (words)
constexpr uint32_t A_TILE_U  = 128 * SA;
constexpr uint32_t B64_U     = 64 * SA;
constexpr uint32_t B128_U    = 128 * SA;
constexpr uint32_t A_BYTES   = A_TILE_U * 4;
constexpr uint32_t UP_STAGE_U = A_TILE_U + 2 * B64_U;   // 9216 words = 36864 B
constexpr uint32_t DN_STAGE_U = A_TILE_U + B128_U;      // 9216 words
constexpr uint32_t UP_STAGE_B = UP_STAGE_U * 4;
constexpr uint32_t DN_STAGE_B = DN_STAGE_U * 4;
constexpr uint32_t UP_SMEM = 2 * UP_STAGE_B + 512;      // 74240  -> 3 CTAs/SM
constexpr uint32_t DN_SMEM = 2 * DN_STAGE_B + 1024;     // 74752  -> 3 CTAs/SM

// ---------------- scratch (static; no allocations allowed) ----------------
__device__ int      g_cnt[MAX_E];
__device__ int      g_tok[MAX_E * MAX_T];
__device__ float    g_gw [MAX_E * MAX_T];
__device__ uint32_t g_act_s[(size_t)MAX_T * MAX_F];
__device__ uint32_t g_act_e[(size_t)MAX_E * MAX_T * MAX_F];
__device__ uint32_t c_x  [(size_t)MAX_T * MAX_H];
__device__ uint32_t c_ws1[(size_t)MAX_F * MAX_H];
__device__ uint32_t c_ws3[(size_t)MAX_F * MAX_H];
__device__ uint32_t c_ws2[(size_t)MAX_H * MAX_F];
__device__ uint32_t c_we1[(size_t)MAX_E * MAX_F * MAX_H];
__device__ uint32_t c_we3[(size_t)MAX_E * MAX_F * MAX_H];
__device__ uint32_t c_we2[(size_t)MAX_E * MAX_H * MAX_F];

// ---------------- helpers ----------------
__device__ __forceinline__ uint32_t s2u(const void* p) {
    uint32_t a;
    asm("{ .reg .u64 t; cvta.to.shared.u64 t, %1; cvt.u32.u64 %0, t; }" : "=r"(a) : "l"(p));
    return a;
}
__device__ __forceinline__ uint4 tf32x4(float4 v) {
    uint4 u;
    asm("cvt.rna.tf32.f32 %0, %1;" : "=r"(u.x) : "f"(v.x));
    asm("cvt.rna.tf32.f32 %0, %1;" : "=r"(u.y) : "f"(v.y));
    asm("cvt.rna.tf32.f32 %0, %1;" : "=r"(u.z) : "f"(v.z));
    asm("cvt.rna.tf32.f32 %0, %1;" : "=r"(u.w) : "f"(v.w));
    return u;
}
__device__ __forceinline__ uint32_t tf32_1(float v) {
    uint32_t u;
    asm("cvt.rna.tf32.f32 %0, %1;" : "=r"(u) : "f"(v));
    return u;
}
__device__ __forceinline__ void mma8(float c[4], const uint32_t a[4], const uint32_t b[2]) {
    asm volatile(
        "mma.sync.aligned.m16n8k8.row.col.f32.tf32.tf32.f32 "
        "{%0,%1,%2,%3}, {%4,%5,%6,%7}, {%8,%9}, {%0,%1,%2,%3};"
        : "+f"(c[0]), "+f"(c[1]), "+f"(c[2]), "+f"(c[3])
        : "r"(a[0]), "r"(a[1]), "r"(a[2]), "r"(a[3]), "r"(b[0]), "r"(b[1]));
}
#define LDSM4(r, a) asm volatile( \
    "ldmatrix.sync.aligned.m8n8.x4.shared.b16 {%0,%1,%2,%3}, [%4];" \
    : "=r"((r)[0]), "=r"((r)[1]), "=r"((r)[2]), "=r"((r)[3]) : "r"(a))
__device__ __forceinline__ void cpa16(uint32_t dst, const uint32_t* src) {
    asm volatile("cp.async.cg.shared.global [%0], [%1], 16;" :: "r"(dst), "l"(src));
}
#define CP_COMMIT() asm volatile("cp.async.commit_group;" ::: "memory")
#define CP_WAIT0()  asm volatile("cp.async.wait_group 0;" ::: "memory")
__device__ __forceinline__ float silu(float x) { return x / (1.f + __expf(-x)); }

// ---------------- kernel: tf32-round a tensor ----------------
__global__ void conv_kernel(const float* __restrict__ in, uint32_t* __restrict__ out, size_t n) {
    size_t i = ((size_t)blockIdx.x * blockDim.x + threadIdx.x) * 4;
    if (i < n) *(uint4*)(out + i) = tf32x4(*(const float4*)(in + i));
}

// ---------------- kernel: zero counters ----------------
__global__ void zero_cnt_kernel() {
    if (threadIdx.x < MAX_E) g_cnt[threadIdx.x] = 0;
}

// ---------------- kernel: zero output ----------------
__global__ void zero_out_kernel(float* __restrict__ out, size_t n) {
    size_t i = ((size_t)blockIdx.x * blockDim.x + threadIdx.x) * 4;
    if (i < n) {
        float4 z; z.x = 0.f; z.y = 0.f; z.z = 0.f; z.w = 0.f;
        *(float4*)(out + i) = z;
    }
}

// ---------------- kernel: gating + top-2 routing (smem-staged x row) ----------------
__global__ void gate_kernel(const float* __restrict__ x,
                            const float* __restrict__ gw,
                            const float* __restrict__ bias,
                            int T, int Hd, int E) {
    int t = blockIdx.x;
    int w = threadIdx.x >> 5, lane = threadIdx.x & 31;
    extern __shared__ float sx[];          // Hd floats + E partials
    float* sc = sx + Hd;
    for (int i = threadIdx.x * 4; i < Hd; i += blockDim.x * 4)
        *(float4*)(sx + i) = *(const float4*)(x + (size_t)t * Hd + i);
    __syncthreads();
    if (w < E) {
        const float* gr = gw + (size_t)w * Hd;
        float s = 0.f;
        for (int i = lane; i < Hd; i += 32) s += sx[i] * gr[i];
        #pragma unroll
        for (int o = 16; o; o >>= 1) s += __shfl_down_sync(0xffffffffu, s, o);
        if (lane == 0) sc[w] = s;
    }
    __syncthreads();
    if (threadIdx.x == 0) {
        float score[MAX_E], rt[MAX_E];
        for (int e = 0; e < E; e++) {
            score[e] = 1.f / (1.f + expf(-sc[e]));
            rt[e] = score[e] + bias[e];
        }
        int b1 = 0;
        for (int e = 1; e < E; e++) if (rt[e] > rt[b1]) b1 = e;
        int b2 = -1;
        for (int e = 0; e < E; e++) {
            if (e == b1) continue;
            if (b2 < 0 || rt[e] > rt[b2]) b2 = e;
        }
        float s1 = score[b1], s2 = score[b2];
        float inv = 1.f / (s1 + s2);
        int p1 = atomicAdd(&g_cnt[b1], 1);
        g_tok[b1 * T + p1] = t; g_gw[b1 * T + p1] = s1 * inv;
        int p2 = atomicAdd(&g_cnt[b2], 1);
        g_tok[b2 * T + p2] = t; g_gw[b2 * T + p2] = s2 * inv;
    }
}

// ---------------- up-projection: dual tf32 mma + fused SwiGLU ----------------
// 128 threads, 4 warps (2x2); warp tile 64x(32+32); 2-stage pipeline; 3 CTAs/SM.
// cp.async for chunk c+1 is issued between j=0 and j=1 so the chunk's first
// LDSM/mma burst is not delayed by LDGSTS issue.
template<bool ROUTED>
__global__ void __launch_bounds__(128, 3)
up_mma(const uint32_t* __restrict__ X, const uint32_t* __restrict__ W1a,
       const uint32_t* __restrict__ W3a, int T, int H, int F)
{
    extern __shared__ __align__(16) uint32_t sm[];
    const int e     = ROUTED ? blockIdx.z : 0;
    const int valid = ROUTED ? g_cnt[e] : T;
    const int row0  = blockIdx.y * BM;
    if (row0 >= valid) return;
    const int col0  = blockIdx.x * 64;
    const int tid   = threadIdx.x, lane = tid & 31, wid = tid >> 5;
    const int wm    = wid >> 1, wn = wid & 1, grp = lane >> 2, tig = lane & 3;
    const uint32_t sb = s2u(sm);

    int* stok = (int*)(sm + 2 * UP_STAGE_U);
    if (ROUTED) {
        int i = row0 + tid; if (i >= valid) i = valid - 1;
        stok[tid] = g_tok[e * T + i];
        __syncthreads();
    }

    const uint32_t* W1 = W1a + (size_t)e * F * H;
    const uint32_t* W3 = W3a + (size_t)e * F * H;
    uint32_t* ACT = ROUTED ? (g_act_e + (size_t)e * T * F) : g_act_s;

    const int r16 = tid >> 3, c4 = tid & 7;
    const uint32_t* b1base = W1 + (size_t)(col0 + r16) * H + c4 * 4;
    const uint32_t* b3base = W3 + (size_t)(col0 + r16) * H + c4 * 4;
    const uint32_t aoff0 = (uint32_t)(r16 * SA + c4 * 4) * 4;
    const uint32_t rstep = 16u * SA * 4u;

    const int lrow = lane & 7;
    uint32_t aAddr[4];
    #pragma unroll
    for (int mt = 0; mt < 4; mt++) {
        int row = wm * 64 + mt * 16 + lrow + 8 * ((lane >> 3) & 1);
        aAddr[mt] = sb + (uint32_t)(row * SA + 4 * (lane >> 4)) * 4;
    }
    uint32_t b1Addr[2], b3Addr[2];
    #pragma unroll
    for (int p = 0; p < 2; p++) {
        int row = wn * 32 + p * 16 + lrow + 8 * (lane >> 4);
        uint32_t off = (uint32_t)(row * SA + 4 * ((lane >> 3) & 1)) * 4;
        b1Addr[p] = sb + A_BYTES + off;
        b3Addr[p] = sb + A_BYTES + B64_U * 4 + off;
    }

    const int nch = H / BK;
    auto load_stage = [&](int c) {
        uint32_t dbase = sb + (uint32_t)(c & 1) * UP_STAGE_B;
        int k0 = c * BK;
        #pragma unroll
        for (int i = 0; i < 8; i++) {
            int r = r16 + 16 * i;
            int tok = ROUTED ? stok[r] : (row0 + r);
            cpa16(dbase + aoff0 + i * rstep, X + (size_t)tok * H + k0 + c4 * 4);
        }
        #pragma unroll
        for (int i = 0; i < 4; i++) {
            cpa16(dbase + A_BYTES + aoff0 + i * rstep, b1base + (size_t)(16 * i) * H + k0);
            cpa16(dbase + A_BYTES + B64_U * 4 + aoff0 + i * rstep, b3base + (size_t)(16 * i) * H + k0);
        }
    };

    float acc1[4][4][4] = {}, acc3[4][4][4] = {};

    auto compute_j = [&](int j, uint32_t stof) {
        uint32_t af[4][4];
        #pragma unroll
        for (int mt = 0; mt < 4; mt++) LDSM4(af[mt], aAddr[mt] + stof + 32u * j);
        uint32_t bf1[2][4], bf3[2][4];
        #pragma unroll
        for (int p = 0; p < 2; p++) {
            LDSM4(bf1[p], b1Addr[p] + stof + 32u * j);
            LDSM4(bf3[p], b3Addr[p] + stof + 32u * j);
        }
        #pragma unroll
        for (int nt = 0; nt < 4; nt++) {
            const int pp = nt >> 1, q = nt & 1;
            uint32_t x1[2] = { bf1[pp][2 * q], bf1[pp][2 * q + 1] };
            uint32_t x3[2] = { bf3[pp][2 * q], bf3[pp][2 * q + 1] };
            #pragma unroll
            for (int mt = 0; mt < 4; mt++) {
                mma8(acc1[mt][nt], af[mt], x1);
                mma8(acc3[mt][nt], af[mt], x3);
            }
        }
    };

    load_stage(0); CP_COMMIT();

    for (int c = 0; c < nch; ++c) {
        CP_WAIT0();
        __syncthreads();
        const uint32_t stof = (uint32_t)(c & 1) * UP_STAGE_B;
        compute_j(0, stof);
        if (c + 1 < nch) { load_stage(c + 1); CP_COMMIT(); }
        compute_j(1, stof);
        compute_j(2, stof);
        compute_j(3, stof);
    }

    // epilogue: SwiGLU, store tf32-rounded pairs
    #pragma unroll
    for (int mt = 0; mt < 4; mt++) {
        #pragma unroll
        for (int nt = 0; nt < 4; nt++) {
            int cA = col0 + wn * 32 + nt * 8 + 2 * tig;
            #pragma unroll
            for (int half = 0; half < 2; half++) {
                int r = row0 + wm * 64 + mt * 16 + grp + 8 * half;
                if (r >= valid) continue;
                float ox = silu(acc1[mt][nt][2 * half])     * acc3[mt][nt][2 * half];
                float oy = silu(acc1[mt][nt][2 * half + 1]) * acc3[mt][nt][2 * half + 1];
                uint2 u; u.x = tf32_1(ox); u.y = tf32_1(oy);
                *(uint2*)(ACT + (size_t)r * F + cA) = u;
            }
        }
    }
}

// ---------------- down-projection: tf32 mma, atomic accumulate into OUT ----------------
// 128 threads, 4 warps (2x2); warp tile 64x64; 2-stage pipeline; 3 CTAs/SM.
template<bool ROUTED>
__global__ void __launch_bounds__(128, 3)
down_mma(const uint32_t* __restrict__ W2a, float* __restrict__ OUT, int T, int H, int F)
{
    extern __shared__ __align__(16) uint32_t sm[];
    const int e     = ROUTED ? blockIdx.z : 0;
    const int valid = ROUTED ? g_cnt[e] : T;
    const int row0  = blockIdx.y * BM;
    if (row0 >= valid) return;
    const int col0  = blockIdx.x * 128;
    const int tid   = threadIdx.x, lane = tid & 31, wid = tid >> 5;
    const int wm    = wid >> 1, wn = wid & 1, grp = lane >> 2, tig = lane & 3;
    const uint32_t sb = s2u(sm);

    int*   stok = (int*)  (sm + 2 * DN_STAGE_U);
    float* sgw  = (float*)(sm + 2 * DN_STAGE_U + 128);
    if (ROUTED) {
        int i = row0 + tid; if (i >= valid) i = valid - 1;
        stok[tid] = g_tok[e * T + i];
        sgw[tid]  = g_gw [e * T + i];
        __syncthreads();
    }

    const uint32_t* ACT = ROUTED ? (g_act_e + (size_t)e * T * F) : g_act_s;
    const uint32_t* W2  = W2a + (size_t)e * H * F;

    const int r16 = tid >> 3, c4 = tid & 7;
    const uint32_t* abase = ACT + (size_t)(row0 + r16) * F + c4 * 4;  // rows >= valid: stale finite scratch, discarded
    const uint32_t* bbase = W2 + (size_t)(col0 + r16) * F + c4 * 4;
    const uint32_t aoff0 = (uint32_t)(r16 * SA + c4 * 4) * 4;
    const uint32_t rstep = 16u * SA * 4u;

    const int lrow = lane & 7;
    uint32_t aAddr[4];
    #pragma unroll
    for (int mt = 0; mt < 4; mt++) {
        int row = wm * 64 + mt * 16 + lrow + 8 * ((lane >> 3) & 1);
        aAddr[mt] = sb + (uint32_t)(row * SA + 4 * (lane >> 4)) * 4;
    }
    uint32_t bAddr[4];
    #pragma unroll
    for (int p = 0; p < 4; p++) {
        int row = wn * 64 + p * 16 + lrow + 8 * (lane >> 4);
        bAddr[p] = sb + A_BYTES + (uint32_t)(row * SA + 4 * ((lane >> 3) & 1)) * 4;
    }

    const int nch = F / BK;
    auto load_stage = [&](int c) {
        uint32_t dbase = sb + (uint32_t)(c & 1) * DN_STAGE_B;
        int k0 = c * BK;
        #pragma unroll
        for (int i = 0; i < 8; i++)
            cpa16(dbase + aoff0 + i * rstep, abase + (size_t)(16 * i) * F + k0);
        #pragma unroll
        for (int i = 0; i < 8; i++)
            cpa16(dbase + A_BYTES + aoff0 + i * rstep, bbase + (size_t)(16 * i) * F + k0);
    };

    float acc[4][8][4] = {};

    auto compute_j = [&](int j, uint32_t stof) {
        uint32_t af[4][4];
        #pragma unroll
        for (int mt = 0; mt < 4; mt++) LDSM4(af[mt], aAddr[mt] + stof + 32u * j);
        uint32_t bf[4][4];
        #pragma unroll
        for (int p = 0; p < 4; p++) LDSM4(bf[p], bAddr[p] + stof + 32u * j);
        #pragma unroll
        for (int nt = 0; nt < 8; nt++) {
            const int pp = nt >> 1, q = nt & 1;
            uint32_t xb[2] = { bf[pp][2 * q], bf[pp][2 * q + 1] };
            #pragma unroll
            for (int mt = 0; mt < 4; mt++) mma8(acc[mt][nt], af[mt], xb);
        }
    };

    load_stage(0); CP_COMMIT();

    for (int c = 0; c < nch; ++c) {
        CP_WAIT0();
        __syncthreads();
        const uint32_t stof = (uint32_t)(c & 1) * DN_STAGE_B;
        compute_j(0, stof);
        if (c + 1 < nch) { load_stage(c + 1); CP_COMMIT(); }
        compute_j(1, stof);
        compute_j(2, stof);
        compute_j(3, stof);
    }

    #pragma unroll
    for (int mt = 0; mt < 4; mt++) {
        #pragma unroll
        for (int nt = 0; nt < 8; nt++) {
            int cA = col0 + wn * 64 + nt * 8 + 2 * tig;
            #pragma unroll
            for (int half = 0; half < 2; half++) {
                int rloc = wm * 64 + mt * 16 + grp + 8 * half;
                int r = row0 + rloc;
                if (r >= valid) continue;
                float v0 = acc[mt][nt][2 * half], v1 = acc[mt][nt][2 * half + 1];
                int tok; float g;
                if (ROUTED) { tok = stok[rloc]; g = sgw[rloc]; }
                else        { tok = r;          g = 1.0f;      }
                float* dst = OUT + (size_t)tok * H + cA;
                atomicAdd(dst,     g * v0);
                atomicAdd(dst + 1, g * v1);
            }
        }
    }
}

// ---------------- launch: forked multi-stream graph (z-batched GEMMs) ----------------
extern "C" void kernel_launch(void* const* d_in, const int* in_sizes, int n_in,
                              void* d_out, int out_size) {
    const float* x    = (const float*)d_in[0];
    const float* gw   = (const float*)d_in[1];
    const float* bias = (const float*)d_in[2];
    const float* ws1  = (const float*)d_in[3];
    const float* ws2  = (const float*)d_in[4];
    const float* ws3  = (const float*)d_in[5];
    const float* we1  = (const float*)d_in[6];
    const float* we2  = (const float*)d_in[7];
    const float* we3  = (const float*)d_in[8];
    float* out = (float*)d_out;

    const int E  = in_sizes[2];
    const int Hd = in_sizes[1] / E;
    const int F  = in_sizes[3] / Hd;
    const int T  = in_sizes[0] / Hd;

    cudaFuncSetAttribute(up_mma<false>,   cudaFuncAttributeMaxDynamicSharedMemorySize, UP_SMEM);
    cudaFuncSetAttribute(up_mma<true>,    cudaFuncAttributeMaxDynamicSharedMemorySize, UP_SMEM);
    cudaFuncSetAttribute(down_mma<false>, cudaFuncAttributeMaxDynamicSharedMemorySize, DN_SMEM);
    cudaFuncSetAttribute(down_mma<true>,  cudaFuncAttributeMaxDynamicSharedMemorySize, DN_SMEM);

    uint32_t *p_cx, *p_cws1, *p_cws3, *p_cws2, *p_cwe1, *p_cwe3, *p_cwe2;
    cudaGetSymbolAddress((void**)&p_cx,   c_x);
    cudaGetSymbolAddress((void**)&p_cws1, c_ws1);
    cudaGetSymbolAddress((void**)&p_cws3, c_ws3);
    cudaGetSymbolAddress((void**)&p_cws2, c_ws2);
    cudaGetSymbolAddress((void**)&p_cwe1, c_we1);
    cudaGetSymbolAddress((void**)&p_cwe3, c_we3);
    cudaGetSymbolAddress((void**)&p_cwe2, c_we2);

    // streams/events created once (host-side resources; no device allocations)
    static cudaStream_t s1 = nullptr, s2 = nullptr, s3 = nullptr;
    static cudaEvent_t e0 = nullptr, ex = nullptr, eg = nullptr, ezo = nullptr;
    static cudaEvent_t e1 = nullptr, e2 = nullptr, evA = nullptr, evB = nullptr;
    if (!s1) {
        cudaStreamCreateWithFlags(&s1, cudaStreamNonBlocking);
        cudaStreamCreateWithFlags(&s2, cudaStreamNonBlocking);
        cudaStreamCreateWithFlags(&s3, cudaStreamNonBlocking);
        cudaEventCreateWithFlags(&e0,  cudaEventDisableTiming);
        cudaEventCreateWithFlags(&ex,  cudaEventDisableTiming);
        cudaEventCreateWithFlags(&eg,  cudaEventDisableTiming);
        cudaEventCreateWithFlags(&ezo, cudaEventDisableTiming);
        cudaEventCreateWithFlags(&e1,  cudaEventDisableTiming);
        cudaEventCreateWithFlags(&e2,  cudaEventDisableTiming);
        cudaEventCreateWithFlags(&evA, cudaEventDisableTiming);
        cudaEventCreateWithFlags(&evB, cudaEventDisableTiming);
    }

    auto conv = [](cudaStream_t s, const float* in, uint32_t* o, size_t n) {
        conv_kernel<<<(unsigned)((n / 4 + 255) / 256), 256, 0, s>>>(in, o, n);
    };
    const size_t nOut = (size_t)T * Hd;

    // ---- fork from capture (default) stream ----
    zero_cnt_kernel<<<1, 32>>>();
    cudaEventRecord(e0, 0);
    cudaStreamWaitEvent(s1, e0, 0);
    cudaStreamWaitEvent(s2, e0, 0);
    cudaStreamWaitEvent(s3, e0, 0);

    // S0: gating immediately (needs raw x only)
    gate_kernel<<<T, 256, (Hd + MAX_E) * 4>>>(x, gw, bias, T, Hd, E);
    cudaEventRecord(eg, 0);

    // S2 head: zero d_out (gates both down kernels)
    zero_out_kernel<<<(unsigned)((nOut / 4 + 255) / 256), 256, 0, s2>>>(out, nOut);
    cudaEventRecord(ezo, s2);

    // S3: expert-weight conversions (concurrent with s1's GEMMs)
    conv(s3, we1, p_cwe1, (size_t)E * F * Hd);
    conv(s3, we3, p_cwe3, (size_t)E * F * Hd);
    cudaEventRecord(evA, s3);                      // up_e gate
    conv(s3, we2, p_cwe2, (size_t)E * Hd * F);
    cudaEventRecord(evB, s3);                      // down_e gate

    // S1: shared-expert chain
    conv(s1, x, p_cx, (size_t)T * Hd);
    cudaEventRecord(ex, s1);                       // converted x (needed by up_e)
    conv(s1, ws1, p_cws1, (size_t)F * Hd);
    conv(s1, ws3, p_cws3, (size_t)F * Hd);
    conv(s1, ws2, p_cws2, (size_t)Hd * F);
    {
        dim3 blk(128);
        up_mma<false><<<dim3(F / 64, T / BM), blk, UP_SMEM, s1>>>(p_cx, p_cws1, p_cws3, T, Hd, F);
        cudaStreamWaitEvent(s1, ezo, 0);           // out zeroed
        down_mma<false><<<dim3(Hd / 128, T / BM), blk, DN_SMEM, s1>>>(p_cws2, out, T, Hd, F);
    }
    cudaEventRecord(e1, s1);

    // S2: routed chain (z-batched full-machine launches)
    cudaStreamWaitEvent(s2, ex, 0);                // converted x
    cudaStreamWaitEvent(s2, eg, 0);                // routing lists
    cudaStreamWaitEvent(s2, evA, 0);               // converted we1/we3
    {
        dim3 blk(128);
        up_mma<true><<<dim3(F / 64, T / BM, E), blk, UP_SMEM, s2>>>(p_cx, p_cwe1, p_cwe3, T, Hd, F);
        cudaStreamWaitEvent(s2, evB, 0);           // converted we2
        down_mma<true><<<dim3(Hd / 128, T / BM, E), blk, DN_SMEM, s2>>>(p_cwe2, out, T, Hd, F);
    }
    cudaEventRecord(e2, s2);

    // ---- join on capture stream ----
    cudaStreamWaitEvent(0, e1, 0);
    cudaStreamWaitEvent(0, e2, 0);
}